// round 2
// baseline (speedup 1.0000x reference)
#include <cuda_runtime.h>
#include <math_constants.h>
#include <cstdint>

// Problem constants
#define Bq   4
#define Sq   1024
#define Dm   1024
#define Hh   16
#define DHd  64
#define Ff   4096
#define NBb  33
#define Ll   6
#define ROWS (Bq*Sq)          // 4096 token rows
#define SCALE_ATTN 0.125f     // 1/sqrt(64)

// ---------------- scratch (device globals; no allocation allowed) ----------------
__device__ float g_x [ROWS*Dm];
__device__ float g_q [ROWS*Dm];
__device__ float g_k [ROWS*Dm];
__device__ float g_v [ROWS*Dm];
__device__ float g_a [ROWS*Dm];
__device__ float g_h [ROWS*Ff];
__device__ float g_qe[Bq*Hh*Sq*NBb];

// ---------------- copy ----------------
__global__ void copy_kernel(const float* __restrict__ in, float* __restrict__ out, int n) {
    int i = blockIdx.x * blockDim.x + threadIdx.x;
    if (i < n) out[i] = in[i];
}

// ---------------- generic tiled GEMM core: C = A@W + bias (+resid) (relu) -------
// A: [M,K] row-major, W: [K,N] row-major, C: [M,N]. 128x128 tile, BK=8, 256 thr, 8x8/thr.
__device__ __forceinline__ void gemm_core(
    const float* __restrict__ A, const float* __restrict__ W,
    const float* __restrict__ bias, const float* __restrict__ resid,
    float* __restrict__ C, int M, int N, int K, bool relu)
{
    __shared__ float As[8][128];
    __shared__ float Bs[8][128];
    int tid = threadIdx.x;
    int tx = tid & 15, ty = tid >> 4;
    int bm = blockIdx.y * 128, bn = blockIdx.x * 128;
    int arow = tid >> 1, acol = (tid & 1) * 4;
    int brow = tid >> 5, bcol = (tid & 31) * 4;
    const float* Ap = A + (size_t)(bm + arow) * K + acol;
    const float* Wp = W + (size_t)brow * N + bn + bcol;

    float acc[8][8];
#pragma unroll
    for (int i = 0; i < 8; i++)
#pragma unroll
        for (int j = 0; j < 8; j++) acc[i][j] = 0.f;

    for (int k0 = 0; k0 < K; k0 += 8) {
        float4 av = *(const float4*)(Ap + k0);
        float4 bv = *(const float4*)(Wp + (size_t)k0 * N);
        As[acol + 0][arow] = av.x;
        As[acol + 1][arow] = av.y;
        As[acol + 2][arow] = av.z;
        As[acol + 3][arow] = av.w;
        *(float4*)&Bs[brow][bcol] = bv;
        __syncthreads();
#pragma unroll
        for (int kk = 0; kk < 8; kk++) {
            float a_[8], b_[8];
            *(float4*)&a_[0] = *(const float4*)&As[kk][ty * 8];
            *(float4*)&a_[4] = *(const float4*)&As[kk][ty * 8 + 4];
            *(float4*)&b_[0] = *(const float4*)&Bs[kk][tx * 8];
            *(float4*)&b_[4] = *(const float4*)&Bs[kk][tx * 8 + 4];
#pragma unroll
            for (int i = 0; i < 8; i++)
#pragma unroll
                for (int j = 0; j < 8; j++)
                    acc[i][j] = fmaf(a_[i], b_[j], acc[i][j]);
        }
        __syncthreads();
    }

#pragma unroll
    for (int i = 0; i < 8; i++) {
        int r = bm + ty * 8 + i;
        size_t base = (size_t)r * N + bn + tx * 8;
#pragma unroll
        for (int j = 0; j < 8; j += 4) {
            float o[4];
#pragma unroll
            for (int jj = 0; jj < 4; jj++) {
                float vv = acc[i][j + jj] + bias[bn + tx * 8 + j + jj];
                if (resid) vv += resid[base + j + jj];
                if (relu)  vv = fmaxf(vv, 0.f);
                o[jj] = vv;
            }
            *(float4*)(C + base + j) = make_float4(o[0], o[1], o[2], o[3]);
        }
    }
}

__global__ void gemm_kernel(const float* __restrict__ A, const float* __restrict__ W,
                            const float* __restrict__ bias, const float* __restrict__ resid,
                            float* __restrict__ C, int M, int N, int K, int relu)
{
    gemm_core(A, W, bias, resid, C, M, N, K, relu != 0);
}

// QKV fused via blockIdx.z (one launch, 3x the blocks -> better occupancy)
__global__ void gemm_qkv_kernel(const float* __restrict__ A,
                                const float* __restrict__ Wq, const float* __restrict__ Wk,
                                const float* __restrict__ Wv,
                                const float* __restrict__ bq, const float* __restrict__ bk,
                                const float* __restrict__ bv,
                                int M, int N, int K)
{
    const float* W; const float* bias; float* C;
    if      (blockIdx.z == 0) { W = Wq; bias = bq; C = g_q; }
    else if (blockIdx.z == 1) { W = Wk; bias = bk; C = g_k; }
    else                      { W = Wv; bias = bv; C = g_v; }
    gemm_core(A, W, bias, nullptr, C, M, N, K, false);
}

// ---------------- qe = q @ Erel^T  ([B,H,S,NB], the rel-e factorization) --------
__global__ void qe_kernel(const float* __restrict__ er)
{
    int idx = blockIdx.x * blockDim.x + threadIdx.x;
    const int total = Bq * Hh * Sq * NBb;
    if (idx >= total) return;
    int nb = idx % NBb;
    int s  = (idx / NBb) % Sq;
    int h  = (idx / (NBb * Sq)) % Hh;
    int b  =  idx / (NBb * Sq * Hh);
    const float* qr = g_q + ((size_t)(b * Sq + s)) * Dm + h * DHd;
    const float* e  = er + nb * DHd;
    float acc = 0.f;
#pragma unroll
    for (int d = 0; d < DHd; d++) acc = fmaf(qr[d], e[d], acc);
    g_qe[idx] = acc;
}

// ---------------- flash attention with relative-position terms -------------------
// grid: (S/32, H, B), 256 threads. Q tile 32 rows, K tile 64 cols.
// static smem: Qs 8K + Ks/P 16K + Vs 16K + Cb 4.22K = 44.3KB (under 48KB, no attr call)
__global__ void attn_kernel(const float* __restrict__ brel, const int* __restrict__ rid)
{
    __shared__ float Qs[64 * 32];     // d-major: Qs[d*32 + qr]
    __shared__ float Ks[64 * 64];     // d-major: Ks[d*64 + kc]; reused as P[qr*64+kc]
    __shared__ float Vs[64 * 64];     // kc-major: Vs[kc*64 + dh]
    __shared__ float Cb[32 * NBb];    // combo: qe-row + brel

    int tid = threadIdx.x;
    int tx = tid & 15, ty = tid >> 4;
    int b = blockIdx.z, h = blockIdx.y;
    int q0 = blockIdx.x * 32;

    size_t qbase = ((size_t)(b * Sq) + q0) * Dm + h * DHd;
    for (int i = tid; i < 32 * 16; i += 256) {
        int r = i >> 4, d4 = (i & 15) * 4;
        float4 t = *(const float4*)(g_q + qbase + (size_t)r * Dm + d4);
        Qs[(d4 + 0) * 32 + r] = t.x;
        Qs[(d4 + 1) * 32 + r] = t.y;
        Qs[(d4 + 2) * 32 + r] = t.z;
        Qs[(d4 + 3) * 32 + r] = t.w;
    }
    for (int i = tid; i < 32 * NBb; i += 256) {
        int r = i / NBb, nb = i - r * NBb;
        Cb[i] = g_qe[(((size_t)(b * Hh + h)) * Sq + q0 + r) * NBb + nb] + brel[h * NBb + nb];
    }

    float m_i[2], l_i[2], o[2][4];
#pragma unroll
    for (int i = 0; i < 2; i++) {
        m_i[i] = -CUDART_INF_F; l_i[i] = 0.f;
#pragma unroll
        for (int j = 0; j < 4; j++) o[i][j] = 0.f;
    }
    __syncthreads();

    for (int k0 = 0; k0 < Sq; k0 += 64) {
        size_t kbase = ((size_t)(b * Sq) + k0) * Dm + h * DHd;
        for (int i = tid; i < 64 * 16; i += 256) {
            int r = i >> 4, d4 = (i & 15) * 4;
            float4 tk = *(const float4*)(g_k + kbase + (size_t)r * Dm + d4);
            Ks[(d4 + 0) * 64 + r] = tk.x;
            Ks[(d4 + 1) * 64 + r] = tk.y;
            Ks[(d4 + 2) * 64 + r] = tk.z;
            Ks[(d4 + 3) * 64 + r] = tk.w;
            float4 tv = *(const float4*)(g_v + kbase + (size_t)r * Dm + d4);
            *(float4*)(Vs + r * 64 + d4) = tv;
        }
        __syncthreads();

        // S = Q K^T (32x64x64); each thread 2x4
        float s4[2][4];
#pragma unroll
        for (int i = 0; i < 2; i++)
#pragma unroll
            for (int j = 0; j < 4; j++) s4[i][j] = 0.f;
#pragma unroll
        for (int d = 0; d < 64; d++) {
            float a0 = Qs[d * 32 + ty * 2 + 0];
            float a1 = Qs[d * 32 + ty * 2 + 1];
            float4 bk = *(const float4*)(Ks + d * 64 + tx * 4);
            s4[0][0] = fmaf(a0, bk.x, s4[0][0]);
            s4[0][1] = fmaf(a0, bk.y, s4[0][1]);
            s4[0][2] = fmaf(a0, bk.z, s4[0][2]);
            s4[0][3] = fmaf(a0, bk.w, s4[0][3]);
            s4[1][0] = fmaf(a1, bk.x, s4[1][0]);
            s4[1][1] = fmaf(a1, bk.y, s4[1][1]);
            s4[1][2] = fmaf(a1, bk.z, s4[1][2]);
            s4[1][3] = fmaf(a1, bk.w, s4[1][3]);
        }

        // rel terms + scale + online softmax (row = 16 lanes with same ty)
#pragma unroll
        for (int i = 0; i < 2; i++) {
            int qr = ty * 2 + i;
            const int* rr = rid + (size_t)(q0 + qr) * Sq + k0 + tx * 4;
            float mt = -CUDART_INF_F;
#pragma unroll
            for (int j = 0; j < 4; j++) {
                float sv = (s4[i][j] + Cb[qr * NBb + rr[j]]) * SCALE_ATTN;
                s4[i][j] = sv;
                mt = fmaxf(mt, sv);
            }
#pragma unroll
            for (int off = 8; off; off >>= 1)
                mt = fmaxf(mt, __shfl_xor_sync(0xffffffffu, mt, off));
            float mnew = fmaxf(m_i[i], mt);
            float fac = __expf(m_i[i] - mnew);
            float rs = 0.f;
#pragma unroll
            for (int j = 0; j < 4; j++) {
                float p = __expf(s4[i][j] - mnew);
                s4[i][j] = p;
                rs += p;
            }
#pragma unroll
            for (int off = 8; off; off >>= 1)
                rs += __shfl_xor_sync(0xffffffffu, rs, off);
            l_i[i] = l_i[i] * fac + rs;
            m_i[i] = mnew;
#pragma unroll
            for (int j = 0; j < 4; j++) o[i][j] *= fac;
        }
        __syncthreads();          // everyone done reading Ks (S-compute)
#pragma unroll
        for (int i = 0; i < 2; i++)
            *(float4*)(Ks + (ty * 2 + i) * 64 + tx * 4) =
                make_float4(s4[i][0], s4[i][1], s4[i][2], s4[i][3]);
        __syncthreads();

        // O += P V  (contract over kc)
#pragma unroll 8
        for (int kc = 0; kc < 64; kc++) {
            float4 vv = *(const float4*)(Vs + kc * 64 + tx * 4);
#pragma unroll
            for (int i = 0; i < 2; i++) {
                float p = Ks[(ty * 2 + i) * 64 + kc];
                o[i][0] = fmaf(p, vv.x, o[i][0]);
                o[i][1] = fmaf(p, vv.y, o[i][1]);
                o[i][2] = fmaf(p, vv.z, o[i][2]);
                o[i][3] = fmaf(p, vv.w, o[i][3]);
            }
        }
        __syncthreads();          // before next tile overwrites Ks/Vs
    }

#pragma unroll
    for (int i = 0; i < 2; i++) {
        float inv = 1.f / l_i[i];
        size_t ob = ((size_t)(b * Sq) + q0 + ty * 2 + i) * Dm + h * DHd + tx * 4;
        *(float4*)(g_a + ob) = make_float4(o[i][0] * inv, o[i][1] * inv,
                                           o[i][2] * inv, o[i][3] * inv);
    }
}

// ---------------- layernorm: 1 block per row, D=1024, 256 threads ----------------
__device__ __forceinline__ float block_sum_256(float val, float* sh) {
#pragma unroll
    for (int off = 16; off; off >>= 1) val += __shfl_xor_sync(0xffffffffu, val, off);
    if ((threadIdx.x & 31) == 0) sh[threadIdx.x >> 5] = val;
    __syncthreads();
    float t = 0.f;
    if (threadIdx.x < 8) t = sh[threadIdx.x];
    if (threadIdx.x < 32) {
#pragma unroll
        for (int off = 4; off; off >>= 1) t += __shfl_xor_sync(0xffffffffu, t, off);
        if (threadIdx.x == 0) sh[0] = t;
    }
    __syncthreads();
    float r = sh[0];
    __syncthreads();
    return r;
}

__global__ void ln_kernel(const float* __restrict__ in, const float* __restrict__ gam,
                          const float* __restrict__ bet, float* __restrict__ out)
{
    __shared__ float sh[8];
    int row = blockIdx.x, tid = threadIdx.x;
    float4 x4 = ((const float4*)(in + (size_t)row * Dm))[tid];
    float s = x4.x + x4.y + x4.z + x4.w;
    float mean = block_sum_256(s, sh) * (1.f / Dm);
    float dx = x4.x - mean, dy = x4.y - mean, dz = x4.z - mean, dw = x4.w - mean;
    float s2 = dx * dx + dy * dy + dz * dz + dw * dw;
    float var = block_sum_256(s2, sh) * (1.f / Dm);
    float inv = rsqrtf(var + 1e-6f);
    int c = tid * 4;
    float4 o;
    o.x = dx * inv * gam[c + 0] + bet[c + 0];
    o.y = dy * inv * gam[c + 1] + bet[c + 1];
    o.z = dz * inv * gam[c + 2] + bet[c + 2];
    o.w = dw * inv * gam[c + 3] + bet[c + 3];
    ((float4*)(out + (size_t)row * Dm))[tid] = o;
}

// ---------------- launch ----------------
extern "C" void kernel_launch(void* const* d_in, const int* in_sizes, int n_in,
                              void* d_out, int out_size)
{
    const float* x_in = (const float*)d_in[0];
    const int*   rid  = (const int*)  d_in[1];
    const float* Wq   = (const float*)d_in[2];
    const float* bqp  = (const float*)d_in[3];
    const float* Wk   = (const float*)d_in[4];
    const float* bkp  = (const float*)d_in[5];
    const float* Wv   = (const float*)d_in[6];
    const float* bvp  = (const float*)d_in[7];
    const float* Wo   = (const float*)d_in[8];
    const float* bop  = (const float*)d_in[9];
    const float* Erel = (const float*)d_in[10];
    const float* Brel = (const float*)d_in[11];
    const float* g1   = (const float*)d_in[12];
    const float* be1  = (const float*)d_in[13];
    const float* g2   = (const float*)d_in[14];
    const float* be2  = (const float*)d_in[15];
    const float* W1   = (const float*)d_in[16];
    const float* b1   = (const float*)d_in[17];
    const float* W2   = (const float*)d_in[18];
    const float* b2   = (const float*)d_in[19];
    float* outp = (float*)d_out;

    static float* x  = nullptr;
    static float* q  = nullptr;
    static float* k  = nullptr;
    static float* v  = nullptr;
    static float* a  = nullptr;
    static float* hb = nullptr;
    if (!x) {
        cudaGetSymbolAddress((void**)&x,  g_x);
        cudaGetSymbolAddress((void**)&q,  g_q);
        cudaGetSymbolAddress((void**)&k,  g_k);
        cudaGetSymbolAddress((void**)&v,  g_v);
        cudaGetSymbolAddress((void**)&a,  g_a);
        cudaGetSymbolAddress((void**)&hb, g_h);
    }

    copy_kernel<<<(ROWS * Dm + 255) / 256, 256>>>(x_in, x, ROWS * Dm);

    for (int l = 0; l < Ll; l++) {
        size_t wdd = (size_t)l * Dm * Dm;
        gemm_qkv_kernel<<<dim3(Dm / 128, ROWS / 128, 3), 256>>>(
            x, Wq + wdd, Wk + wdd, Wv + wdd,
            bqp + l * Dm, bkp + l * Dm, bvp + l * Dm,
            ROWS, Dm, Dm);

        const int qetot = Bq * Hh * Sq * NBb;
        qe_kernel<<<(qetot + 255) / 256, 256>>>(Erel + (size_t)l * NBb * DHd);

        attn_kernel<<<dim3(Sq / 32, Hh, Bq), 256>>>(Brel + (size_t)l * Hh * NBb, rid);

        // y = a@Wo + bo + x   (residual fused)  -> q (q is free now)
        gemm_kernel<<<dim3(Dm / 128, ROWS / 128), 256>>>(
            a, Wo + wdd, bop + l * Dm, x, q, ROWS, Dm, Dm, 0);

        // ff_in = LN1(y) -> k
        ln_kernel<<<ROWS, 256>>>(q, g1 + l * Dm, be1 + l * Dm, k);

        // h = relu(ff_in@W1 + b1)
        gemm_kernel<<<dim3(Ff / 128, ROWS / 128), 256>>>(
            k, W1 + (size_t)l * Dm * Ff, b1 + l * Ff, nullptr, hb, ROWS, Ff, Dm, 1);

        // y2 = h@W2 + b2 + ff_in -> v
        gemm_kernel<<<dim3(Dm / 128, ROWS / 128), 256>>>(
            hb, W2 + (size_t)l * Ff * Dm, b2 + l * Dm, k, v, ROWS, Dm, Ff, 0);

        // x = LN2(y2)   (last layer writes directly to output)
        ln_kernel<<<ROWS, 256>>>(v, g2 + l * Dm, be2 + l * Dm, (l == Ll - 1) ? outp : x);
    }
}

// round 4
// speedup vs baseline: 1.2850x; 1.2850x over previous
#include <cuda_runtime.h>
#include <cuda_bf16.h>
#include <math_constants.h>
#include <cstdint>

// Problem constants
#define Bq   4
#define Sq   1024
#define Dm   1024
#define Hh   16
#define DHd  64
#define Ff   4096
#define NBb  33
#define Ll   6
#define ROWS (Bq*Sq)          // 4096 token rows
#define SCALE_ATTN 0.125f     // 1/sqrt(64)

// ---------------- scratch (device globals; no allocation allowed) ----------------
__device__ float g_x [ROWS*Dm];
__device__ float g_q [ROWS*Dm];
__device__ float g_k [ROWS*Dm];
__device__ float g_v [ROWS*Dm];
__device__ float g_a [ROWS*Dm];
__device__ float g_h [ROWS*Ff];
__device__ float g_qe[Bq*Hh*Sq*NBb];

// ---------------- copy ----------------
__global__ void copy_kernel(const float* __restrict__ in, float* __restrict__ out, int n) {
    int i = blockIdx.x * blockDim.x + threadIdx.x;
    if (i < n) out[i] = in[i];
}

// ---------------- bf16x2-split tensor-core GEMM ---------------------------------
// C = A@W + bias (+resid) (relu).  A:[M,K] row-major fp32, W:[K,N] row-major fp32.
// Split each operand into hi+lo bf16; accumulate hi*hi + hi*lo + lo*hi in fp32 via
// mma.sync.m16n8k16. Effective precision ~2^-16 per product.
// CTA tile 128x128, BK=32, 256 threads = 8 warps (4m x 2n), warp tile 32x64.
#define PADk 40   // bf16 elems per smem row (32 + 8 pad -> conflict-free frag loads)

__device__ __forceinline__ void mma_bf16(float* c, const uint32_t* a, uint32_t b0, uint32_t b1) {
    asm volatile(
        "mma.sync.aligned.m16n8k16.row.col.f32.bf16.bf16.f32 "
        "{%0,%1,%2,%3}, {%4,%5,%6,%7}, {%8,%9}, {%0,%1,%2,%3};\n"
        : "+f"(c[0]), "+f"(c[1]), "+f"(c[2]), "+f"(c[3])
        : "r"(a[0]), "r"(a[1]), "r"(a[2]), "r"(a[3]), "r"(b0), "r"(b1));
}

__device__ __forceinline__ void gemm_bf_core(
    const float* __restrict__ A, const float* __restrict__ W,
    const float* __restrict__ bias, const float* __restrict__ resid,
    float* __restrict__ C, int M, int N, int K, bool relu)
{
    __shared__ __nv_bfloat16 Ah[128 * PADk];
    __shared__ __nv_bfloat16 Al[128 * PADk];
    __shared__ __nv_bfloat16 Bh[128 * PADk];
    __shared__ __nv_bfloat16 Bl[128 * PADk];

    const int tid  = threadIdx.x;
    const int lane = tid & 31;
    const int warp = tid >> 5;
    const int wm   = warp >> 1;       // 0..3
    const int wn   = warp & 1;        // 0..1
    const int g    = lane >> 2;       // group id 0..7
    const int tig  = lane & 3;        // thread-in-group

    const int bm = blockIdx.y * 128, bn = blockIdx.x * 128;

    // A load mapping: row = tid/2, 16 k's starting at (tid&1)*16
    const int arow = tid >> 1, akb = (tid & 1) * 16;
    // B load mapping: krow = tid/8, 16 n's starting at (tid&7)*16
    const int bkr = tid >> 3, bnb = (tid & 7) * 16;

    float acc[2][8][4];
#pragma unroll
    for (int i = 0; i < 2; i++)
#pragma unroll
        for (int j = 0; j < 8; j++)
#pragma unroll
            for (int c = 0; c < 4; c++) acc[i][j][c] = 0.f;

    for (int k0 = 0; k0 < K; k0 += 32) {
        // ---- load A tile 128x32, split hi/lo, store [row][k] ----
#pragma unroll
        for (int i = 0; i < 4; i++) {
            const float4 av = *(const float4*)(A + (size_t)(bm + arow) * K + k0 + akb + i * 4);
            float f[4] = {av.x, av.y, av.z, av.w};
            __nv_bfloat16 h[4], lo[4];
#pragma unroll
            for (int e = 0; e < 4; e++) {
                h[e]  = __float2bfloat16_rn(f[e]);
                lo[e] = __float2bfloat16_rn(f[e] - __bfloat162float(h[e]));
            }
            const int off = arow * PADk + akb + i * 4;
            *(__nv_bfloat162*)(Ah + off)     = __nv_bfloat162(h[0],  h[1]);
            *(__nv_bfloat162*)(Ah + off + 2) = __nv_bfloat162(h[2],  h[3]);
            *(__nv_bfloat162*)(Al + off)     = __nv_bfloat162(lo[0], lo[1]);
            *(__nv_bfloat162*)(Al + off + 2) = __nv_bfloat162(lo[2], lo[3]);
        }
        // ---- load B tile 32x128, split hi/lo, transpose to [n][k] ----
#pragma unroll
        for (int i = 0; i < 4; i++) {
            const float4 wv = *(const float4*)(W + (size_t)(k0 + bkr) * N + bn + bnb + i * 4);
            float f[4] = {wv.x, wv.y, wv.z, wv.w};
#pragma unroll
            for (int e = 0; e < 4; e++) {
                const __nv_bfloat16 h = __float2bfloat16_rn(f[e]);
                const __nv_bfloat16 lo = __float2bfloat16_rn(f[e] - __bfloat162float(h));
                const int n = bnb + i * 4 + e;
                Bh[n * PADk + bkr] = h;
                Bl[n * PADk + bkr] = lo;
            }
        }
        __syncthreads();

        // ---- 2 k-steps of m16n8k16 ----
#pragma unroll
        for (int ks = 0; ks < 2; ks++) {
            const int kk = ks * 16;
            uint32_t ah[2][4], al[2][4];
#pragma unroll
            for (int mf = 0; mf < 2; mf++) {
                const int r = wm * 32 + mf * 16 + g;
                const int c0 = kk + 2 * tig;
                ah[mf][0] = *(const uint32_t*)(Ah + r * PADk + c0);
                ah[mf][1] = *(const uint32_t*)(Ah + (r + 8) * PADk + c0);
                ah[mf][2] = *(const uint32_t*)(Ah + r * PADk + c0 + 8);
                ah[mf][3] = *(const uint32_t*)(Ah + (r + 8) * PADk + c0 + 8);
                al[mf][0] = *(const uint32_t*)(Al + r * PADk + c0);
                al[mf][1] = *(const uint32_t*)(Al + (r + 8) * PADk + c0);
                al[mf][2] = *(const uint32_t*)(Al + r * PADk + c0 + 8);
                al[mf][3] = *(const uint32_t*)(Al + (r + 8) * PADk + c0 + 8);
            }
#pragma unroll
            for (int nf = 0; nf < 8; nf++) {
                const int n = wn * 64 + nf * 8 + g;
                const int c0 = kk + 2 * tig;
                const uint32_t bh0 = *(const uint32_t*)(Bh + n * PADk + c0);
                const uint32_t bh1 = *(const uint32_t*)(Bh + n * PADk + c0 + 8);
                const uint32_t bl0 = *(const uint32_t*)(Bl + n * PADk + c0);
                const uint32_t bl1 = *(const uint32_t*)(Bl + n * PADk + c0 + 8);
#pragma unroll
                for (int mf = 0; mf < 2; mf++) {
                    mma_bf16(acc[mf][nf], ah[mf], bh0, bh1);   // hi*hi
                    mma_bf16(acc[mf][nf], ah[mf], bl0, bl1);   // hi*lo
                    mma_bf16(acc[mf][nf], al[mf], bh0, bh1);   // lo*hi
                }
            }
        }
        __syncthreads();
    }

    // ---- epilogue: bias (+resid) (relu), fp32 float2 stores ----
#pragma unroll
    for (int mf = 0; mf < 2; mf++) {
#pragma unroll
        for (int nf = 0; nf < 8; nf++) {
            const int r0 = bm + wm * 32 + mf * 16 + g;
            const int cc = bn + wn * 64 + nf * 8 + 2 * tig;
            const float bs0 = bias[cc], bs1 = bias[cc + 1];
            float v0 = acc[mf][nf][0] + bs0;
            float v1 = acc[mf][nf][1] + bs1;
            float v2 = acc[mf][nf][2] + bs0;
            float v3 = acc[mf][nf][3] + bs1;
            const size_t i0 = (size_t)r0 * N + cc;
            const size_t i1 = (size_t)(r0 + 8) * N + cc;
            if (resid) {
                const float2 r0v = *(const float2*)(resid + i0);
                const float2 r1v = *(const float2*)(resid + i1);
                v0 += r0v.x; v1 += r0v.y; v2 += r1v.x; v3 += r1v.y;
            }
            if (relu) {
                v0 = fmaxf(v0, 0.f); v1 = fmaxf(v1, 0.f);
                v2 = fmaxf(v2, 0.f); v3 = fmaxf(v3, 0.f);
            }
            *(float2*)(C + i0) = make_float2(v0, v1);
            *(float2*)(C + i1) = make_float2(v2, v3);
        }
    }
}

__global__ __launch_bounds__(256) void gemm_bf_kernel(
    const float* __restrict__ A, const float* __restrict__ W,
    const float* __restrict__ bias, const float* __restrict__ resid,
    float* __restrict__ C, int M, int N, int K, int relu)
{
    gemm_bf_core(A, W, bias, resid, C, M, N, K, relu != 0);
}

// QKV fused via blockIdx.z
__global__ __launch_bounds__(256) void gemm_bf_qkv_kernel(
    const float* __restrict__ A,
    const float* __restrict__ Wq, const float* __restrict__ Wk, const float* __restrict__ Wv,
    const float* __restrict__ bq, const float* __restrict__ bk, const float* __restrict__ bv,
    int M, int N, int K)
{
    const float* W; const float* bias; float* C;
    if      (blockIdx.z == 0) { W = Wq; bias = bq; C = g_q; }
    else if (blockIdx.z == 1) { W = Wk; bias = bk; C = g_k; }
    else                      { W = Wv; bias = bv; C = g_v; }
    gemm_bf_core(A, W, bias, nullptr, C, M, N, K, false);
}

// ---------------- qe = q @ Erel^T  ([B,H,S,NB], the rel-e factorization) --------
__global__ void qe_kernel(const float* __restrict__ er)
{
    int idx = blockIdx.x * blockDim.x + threadIdx.x;
    const int total = Bq * Hh * Sq * NBb;
    if (idx >= total) return;
    int nb = idx % NBb;
    int s  = (idx / NBb) % Sq;
    int h  = (idx / (NBb * Sq)) % Hh;
    int b  =  idx / (NBb * Sq * Hh);
    const float* qr = g_q + ((size_t)(b * Sq + s)) * Dm + h * DHd;
    const float* e  = er + nb * DHd;
    float acc = 0.f;
#pragma unroll
    for (int d = 0; d < DHd; d++) acc = fmaf(qr[d], e[d], acc);
    g_qe[idx] = acc;
}

// ---------------- flash attention with relative-position terms -------------------
// grid: (S/32, H, B), 256 threads. Q tile 32 rows, K tile 64 cols. 44.3KB static smem.
__global__ void attn_kernel(const float* __restrict__ brel, const int* __restrict__ rid)
{
    __shared__ float Qs[64 * 32];     // d-major: Qs[d*32 + qr]
    __shared__ float Ks[64 * 64];     // d-major: Ks[d*64 + kc]; reused as P[qr*64+kc]
    __shared__ float Vs[64 * 64];     // kc-major: Vs[kc*64 + dh]
    __shared__ float Cb[32 * NBb];    // combo: qe-row + brel

    int tid = threadIdx.x;
    int tx = tid & 15, ty = tid >> 4;
    int b = blockIdx.z, h = blockIdx.y;
    int q0 = blockIdx.x * 32;

    size_t qbase = ((size_t)(b * Sq) + q0) * Dm + h * DHd;
    for (int i = tid; i < 32 * 16; i += 256) {
        int r = i >> 4, d4 = (i & 15) * 4;
        float4 t = *(const float4*)(g_q + qbase + (size_t)r * Dm + d4);
        Qs[(d4 + 0) * 32 + r] = t.x;
        Qs[(d4 + 1) * 32 + r] = t.y;
        Qs[(d4 + 2) * 32 + r] = t.z;
        Qs[(d4 + 3) * 32 + r] = t.w;
    }
    for (int i = tid; i < 32 * NBb; i += 256) {
        int r = i / NBb, nb = i - r * NBb;
        Cb[i] = g_qe[(((size_t)(b * Hh + h)) * Sq + q0 + r) * NBb + nb] + brel[h * NBb + nb];
    }

    float m_i[2], l_i[2], o[2][4];
#pragma unroll
    for (int i = 0; i < 2; i++) {
        m_i[i] = -CUDART_INF_F; l_i[i] = 0.f;
#pragma unroll
        for (int j = 0; j < 4; j++) o[i][j] = 0.f;
    }
    __syncthreads();

    for (int k0 = 0; k0 < Sq; k0 += 64) {
        size_t kbase = ((size_t)(b * Sq) + k0) * Dm + h * DHd;
        for (int i = tid; i < 64 * 16; i += 256) {
            int r = i >> 4, d4 = (i & 15) * 4;
            float4 tk = *(const float4*)(g_k + kbase + (size_t)r * Dm + d4);
            Ks[(d4 + 0) * 64 + r] = tk.x;
            Ks[(d4 + 1) * 64 + r] = tk.y;
            Ks[(d4 + 2) * 64 + r] = tk.z;
            Ks[(d4 + 3) * 64 + r] = tk.w;
            float4 tv = *(const float4*)(g_v + kbase + (size_t)r * Dm + d4);
            *(float4*)(Vs + r * 64 + d4) = tv;
        }
        __syncthreads();

        float s4[2][4];
#pragma unroll
        for (int i = 0; i < 2; i++)
#pragma unroll
            for (int j = 0; j < 4; j++) s4[i][j] = 0.f;
#pragma unroll
        for (int d = 0; d < 64; d++) {
            float a0 = Qs[d * 32 + ty * 2 + 0];
            float a1 = Qs[d * 32 + ty * 2 + 1];
            float4 bk = *(const float4*)(Ks + d * 64 + tx * 4);
            s4[0][0] = fmaf(a0, bk.x, s4[0][0]);
            s4[0][1] = fmaf(a0, bk.y, s4[0][1]);
            s4[0][2] = fmaf(a0, bk.z, s4[0][2]);
            s4[0][3] = fmaf(a0, bk.w, s4[0][3]);
            s4[1][0] = fmaf(a1, bk.x, s4[1][0]);
            s4[1][1] = fmaf(a1, bk.y, s4[1][1]);
            s4[1][2] = fmaf(a1, bk.z, s4[1][2]);
            s4[1][3] = fmaf(a1, bk.w, s4[1][3]);
        }

#pragma unroll
        for (int i = 0; i < 2; i++) {
            int qr = ty * 2 + i;
            const int* rr = rid + (size_t)(q0 + qr) * Sq + k0 + tx * 4;
            float mt = -CUDART_INF_F;
#pragma unroll
            for (int j = 0; j < 4; j++) {
                float sv = (s4[i][j] + Cb[qr * NBb + rr[j]]) * SCALE_ATTN;
                s4[i][j] = sv;
                mt = fmaxf(mt, sv);
            }
#pragma unroll
            for (int off = 8; off; off >>= 1)
                mt = fmaxf(mt, __shfl_xor_sync(0xffffffffu, mt, off));
            float mnew = fmaxf(m_i[i], mt);
            float fac = __expf(m_i[i] - mnew);
            float rs = 0.f;
#pragma unroll
            for (int j = 0; j < 4; j++) {
                float p = __expf(s4[i][j] - mnew);
                s4[i][j] = p;
                rs += p;
            }
#pragma unroll
            for (int off = 8; off; off >>= 1)
                rs += __shfl_xor_sync(0xffffffffu, rs, off);
            l_i[i] = l_i[i] * fac + rs;
            m_i[i] = mnew;
#pragma unroll
            for (int j = 0; j < 4; j++) o[i][j] *= fac;
        }
        __syncthreads();
#pragma unroll
        for (int i = 0; i < 2; i++)
            *(float4*)(Ks + (ty * 2 + i) * 64 + tx * 4) =
                make_float4(s4[i][0], s4[i][1], s4[i][2], s4[i][3]);
        __syncthreads();

#pragma unroll 8
        for (int kc = 0; kc < 64; kc++) {
            float4 vv = *(const float4*)(Vs + kc * 64 + tx * 4);
#pragma unroll
            for (int i = 0; i < 2; i++) {
                float p = Ks[(ty * 2 + i) * 64 + kc];
                o[i][0] = fmaf(p, vv.x, o[i][0]);
                o[i][1] = fmaf(p, vv.y, o[i][1]);
                o[i][2] = fmaf(p, vv.z, o[i][2]);
                o[i][3] = fmaf(p, vv.w, o[i][3]);
            }
        }
        __syncthreads();
    }

#pragma unroll
    for (int i = 0; i < 2; i++) {
        float inv = 1.f / l_i[i];
        size_t ob = ((size_t)(b * Sq) + q0 + ty * 2 + i) * Dm + h * DHd + tx * 4;
        *(float4*)(g_a + ob) = make_float4(o[i][0] * inv, o[i][1] * inv,
                                           o[i][2] * inv, o[i][3] * inv);
    }
}

// ---------------- layernorm: 1 block per row, D=1024, 256 threads ----------------
__device__ __forceinline__ float block_sum_256(float val, float* sh) {
#pragma unroll
    for (int off = 16; off; off >>= 1) val += __shfl_xor_sync(0xffffffffu, val, off);
    if ((threadIdx.x & 31) == 0) sh[threadIdx.x >> 5] = val;
    __syncthreads();
    float t = 0.f;
    if (threadIdx.x < 8) t = sh[threadIdx.x];
    if (threadIdx.x < 32) {
#pragma unroll
        for (int off = 4; off; off >>= 1) t += __shfl_xor_sync(0xffffffffu, t, off);
        if (threadIdx.x == 0) sh[0] = t;
    }
    __syncthreads();
    float r = sh[0];
    __syncthreads();
    return r;
}

__global__ void ln_kernel(const float* __restrict__ in, const float* __restrict__ gam,
                          const float* __restrict__ bet, float* __restrict__ out)
{
    __shared__ float sh[8];
    int row = blockIdx.x, tid = threadIdx.x;
    float4 x4 = ((const float4*)(in + (size_t)row * Dm))[tid];
    float s = x4.x + x4.y + x4.z + x4.w;
    float mean = block_sum_256(s, sh) * (1.f / Dm);
    float dx = x4.x - mean, dy = x4.y - mean, dz = x4.z - mean, dw = x4.w - mean;
    float s2 = dx * dx + dy * dy + dz * dz + dw * dw;
    float var = block_sum_256(s2, sh) * (1.f / Dm);
    float inv = rsqrtf(var + 1e-6f);
    int c = tid * 4;
    float4 o;
    o.x = dx * inv * gam[c + 0] + bet[c + 0];
    o.y = dy * inv * gam[c + 1] + bet[c + 1];
    o.z = dz * inv * gam[c + 2] + bet[c + 2];
    o.w = dw * inv * gam[c + 3] + bet[c + 3];
    ((float4*)(out + (size_t)row * Dm))[tid] = o;
}

// ---------------- launch ----------------
extern "C" void kernel_launch(void* const* d_in, const int* in_sizes, int n_in,
                              void* d_out, int out_size)
{
    const float* x_in = (const float*)d_in[0];
    const int*   rid  = (const int*)  d_in[1];
    const float* Wq   = (const float*)d_in[2];
    const float* bqp  = (const float*)d_in[3];
    const float* Wk   = (const float*)d_in[4];
    const float* bkp  = (const float*)d_in[5];
    const float* Wv   = (const float*)d_in[6];
    const float* bvp  = (const float*)d_in[7];
    const float* Wo   = (const float*)d_in[8];
    const float* bop  = (const float*)d_in[9];
    const float* Erel = (const float*)d_in[10];
    const float* Brel = (const float*)d_in[11];
    const float* g1   = (const float*)d_in[12];
    const float* be1  = (const float*)d_in[13];
    const float* g2   = (const float*)d_in[14];
    const float* be2  = (const float*)d_in[15];
    const float* W1   = (const float*)d_in[16];
    const float* b1   = (const float*)d_in[17];
    const float* W2   = (const float*)d_in[18];
    const float* b2   = (const float*)d_in[19];
    float* outp = (float*)d_out;

    float *x, *q, *k, *v, *a, *hb;
    cudaGetSymbolAddress((void**)&x,  g_x);
    cudaGetSymbolAddress((void**)&q,  g_q);
    cudaGetSymbolAddress((void**)&k,  g_k);
    cudaGetSymbolAddress((void**)&v,  g_v);
    cudaGetSymbolAddress((void**)&a,  g_a);
    cudaGetSymbolAddress((void**)&hb, g_h);

    copy_kernel<<<(ROWS * Dm + 255) / 256, 256>>>(x_in, x, ROWS * Dm);

    for (int l = 0; l < Ll; l++) {
        size_t wdd = (size_t)l * Dm * Dm;
        gemm_bf_qkv_kernel<<<dim3(Dm / 128, ROWS / 128, 3), 256>>>(
            x, Wq + wdd, Wk + wdd, Wv + wdd,
            bqp + l * Dm, bkp + l * Dm, bvp + l * Dm,
            ROWS, Dm, Dm);

        const int qetot = Bq * Hh * Sq * NBb;
        qe_kernel<<<(qetot + 255) / 256, 256>>>(Erel + (size_t)l * NBb * DHd);

        attn_kernel<<<dim3(Sq / 32, Hh, Bq), 256>>>(Brel + (size_t)l * Hh * NBb, rid);

        // y = a@Wo + bo + x   (residual fused)  -> q (q is free now)
        gemm_bf_kernel<<<dim3(Dm / 128, ROWS / 128), 256>>>(
            a, Wo + wdd, bop + l * Dm, x, q, ROWS, Dm, Dm, 0);

        // ff_in = LN1(y) -> k
        ln_kernel<<<ROWS, 256>>>(q, g1 + l * Dm, be1 + l * Dm, k);

        // h = relu(ff_in@W1 + b1)
        gemm_bf_kernel<<<dim3(Ff / 128, ROWS / 128), 256>>>(
            k, W1 + (size_t)l * Dm * Ff, b1 + l * Ff, nullptr, hb, ROWS, Ff, Dm, 1);

        // y2 = h@W2 + b2 + ff_in -> v
        gemm_bf_kernel<<<dim3(Dm / 128, ROWS / 128), 256>>>(
            hb, W2 + (size_t)l * Ff * Dm, b2 + l * Dm, k, v, ROWS, Dm, Ff, 0);

        // x = LN2(y2)   (last layer writes directly to output)
        ln_kernel<<<ROWS, 256>>>(v, g2 + l * Dm, be2 + l * Dm, (l == Ll - 1) ? outp : x);
    }
}

// round 5
// speedup vs baseline: 1.8294x; 1.4236x over previous
#include <cuda_runtime.h>
#include <cuda_bf16.h>
#include <math_constants.h>
#include <cstdint>

// Problem constants
#define Bq   4
#define Sq   1024
#define Dm   1024
#define Hh   16
#define DHd  64
#define Ff   4096
#define NBb  33
#define Ll   6
#define ROWS (Bq*Sq)
#define SCALE_ATTN 0.125f

// ---------------- scratch (device globals) ----------------
__device__ float g_x [ROWS*Dm];     // layer input fp32 (residual)
__device__ float g_y [ROWS*Dm];     // q / post-Wo fp32
__device__ float g_k [ROWS*Dm];     // k / ff_in fp32
__device__ float g_v [ROWS*Dm];     // v / y2 fp32
__device__ float g_qe[Bq*Hh*Sq*NBb];

__device__ __nv_bfloat16 g_xh [ROWS*Dm], g_xl [ROWS*Dm];   // x split (QKV A operand)
__device__ __nv_bfloat16 g_ah [ROWS*Dm], g_al [ROWS*Dm];   // attn out split (Wo A)
__device__ __nv_bfloat16 g_ffh[ROWS*Dm], g_ffl[ROWS*Dm];   // ff_in split (W1 A)
__device__ __nv_bfloat16 g_hh [ROWS*Ff], g_hl [ROWS*Ff];   // ffn mid split (W2 A)

// transposed bf16 weights: [N][K]
__device__ __nv_bfloat16 g_wT4h[Ll*4*Dm*Dm], g_wT4l[Ll*4*Dm*Dm];  // Wq,Wk,Wv,Wo
__device__ __nv_bfloat16 g_w1Th[Ll*Ff*Dm],  g_w1Tl[Ll*Ff*Dm];     // W1^T [F][D]
__device__ __nv_bfloat16 g_w2Th[Ll*Dm*Ff],  g_w2Tl[Ll*Dm*Ff];     // W2^T [D][F]

__device__ __forceinline__ void bsplit(float f, __nv_bfloat16& h, __nv_bfloat16& l) {
    h = __float2bfloat16_rn(f);
    l = __float2bfloat16_rn(f - __bfloat162float(h));
}

// ---------------- weight transpose + split: W[K][N] -> Th/Tl[N][K] ----------------
__global__ void wconv_kernel(const float* __restrict__ W,
                             __nv_bfloat16* __restrict__ Th, __nv_bfloat16* __restrict__ Tl,
                             int K, int N)
{
    __shared__ float t[32][33];
    int n0 = blockIdx.x * 32, k0 = blockIdx.y * 32;
    int tx = threadIdx.x, ty = threadIdx.y;     // 32 x 8
#pragma unroll
    for (int i = 0; i < 4; i++)
        t[ty + 8 * i][tx] = W[(size_t)(k0 + ty + 8 * i) * N + n0 + tx];
    __syncthreads();
#pragma unroll
    for (int i = 0; i < 4; i++) {
        float f = t[tx][ty + 8 * i];            // W[k0+tx][n0+ty+8i]
        int n = n0 + ty + 8 * i, k = k0 + tx;
        __nv_bfloat16 h, l; bsplit(f, h, l);
        Th[(size_t)n * K + k] = h;
        Tl[(size_t)n * K + k] = l;
    }
}

// ---------------- copy + split ----------------
__global__ void copy_split_kernel(const float* __restrict__ in, float* __restrict__ out,
                                  __nv_bfloat16* __restrict__ oh, __nv_bfloat16* __restrict__ ol,
                                  int n)
{
    int i = blockIdx.x * blockDim.x + threadIdx.x;
    if (i < n) {
        float f = in[i];
        out[i] = f;
        __nv_bfloat16 h, l; bsplit(f, h, l);
        oh[i] = h; ol[i] = l;
    }
}

// ---------------- bf16-operand tensor-core GEMM, cp.async 2-stage ---------------
// C = Ah+Al @ (Bh+Bl)^T + bias (+resid)(relu); A[M][K] bf16 hi/lo, B[N][K] bf16 hi/lo.
// CTA 128x128, chunk BK=16, 256 thr = 8 warps (4m x 2n), warp tile 32x64.
// 3 MMAs per fragment pair: hi*hi + hi*lo + lo*hi.
#define PADk 24   // bf16 per smem row: 16 + 8 pad (48B rows: 16B-aligned, conflict-free)

__device__ __forceinline__ void mma_bf16(float* c, const uint32_t* a, uint32_t b0, uint32_t b1) {
    asm volatile(
        "mma.sync.aligned.m16n8k16.row.col.f32.bf16.bf16.f32 "
        "{%0,%1,%2,%3}, {%4,%5,%6,%7}, {%8,%9}, {%0,%1,%2,%3};\n"
        : "+f"(c[0]), "+f"(c[1]), "+f"(c[2]), "+f"(c[3])
        : "r"(a[0]), "r"(a[1]), "r"(a[2]), "r"(a[3]), "r"(b0), "r"(b1));
}

__device__ __forceinline__ void cpasync16(__nv_bfloat16* dst, const __nv_bfloat16* src) {
    uint32_t s = (uint32_t)__cvta_generic_to_shared(dst);
    asm volatile("cp.async.cg.shared.global [%0], [%1], 16;\n" :: "r"(s), "l"(src));
}

__device__ __forceinline__ void gemm16_core(
    const __nv_bfloat16* __restrict__ Ah, const __nv_bfloat16* __restrict__ Al,
    const __nv_bfloat16* __restrict__ Bh, const __nv_bfloat16* __restrict__ Bl,
    const float* __restrict__ bias, const float* __restrict__ resid,
    float* __restrict__ C, __nv_bfloat16* __restrict__ Ch, __nv_bfloat16* __restrict__ Cl,
    int M, int N, int K, bool relu)
{
    __shared__ __nv_bfloat16 sAh[2][128 * PADk], sAl[2][128 * PADk];
    __shared__ __nv_bfloat16 sBh[2][128 * PADk], sBl[2][128 * PADk];

    const int tid  = threadIdx.x;
    const int lane = tid & 31;
    const int warp = tid >> 5;
    const int wm   = warp >> 1;
    const int wn   = warp & 1;
    const int g    = lane >> 2;
    const int tig  = lane & 3;

    const int bm = blockIdx.y * 128, bn = blockIdx.x * 128;

    const int prow = tid >> 1, phalf = (tid & 1) * 8;   // cp.async mapping

    float acc[2][8][4];
#pragma unroll
    for (int i = 0; i < 2; i++)
#pragma unroll
        for (int j = 0; j < 8; j++)
#pragma unroll
            for (int c = 0; c < 4; c++) acc[i][j][c] = 0.f;

    const int nck = K >> 4;
    // prefetch chunk 0 -> stage 0
    {
        const size_t goA = (size_t)(bm + prow) * K + phalf;
        const size_t goB = (size_t)(bn + prow) * K + phalf;
        const int so = prow * PADk + phalf;
        cpasync16(&sAh[0][so], Ah + goA);
        cpasync16(&sAl[0][so], Al + goA);
        cpasync16(&sBh[0][so], Bh + goB);
        cpasync16(&sBl[0][so], Bl + goB);
    }
    asm volatile("cp.async.commit_group;\n");

    for (int kc = 0; kc < nck; kc++) {
        asm volatile("cp.async.wait_group 0;\n");
        __syncthreads();
        if (kc + 1 < nck) {
            const int st = (kc + 1) & 1;
            const size_t goA = (size_t)(bm + prow) * K + (kc + 1) * 16 + phalf;
            const size_t goB = (size_t)(bn + prow) * K + (kc + 1) * 16 + phalf;
            const int so = prow * PADk + phalf;
            cpasync16(&sAh[st][so], Ah + goA);
            cpasync16(&sAl[st][so], Al + goA);
            cpasync16(&sBh[st][so], Bh + goB);
            cpasync16(&sBl[st][so], Bl + goB);
            asm volatile("cp.async.commit_group;\n");
        }
        const int st = kc & 1;
        const __nv_bfloat16* Ahs = sAh[st];
        const __nv_bfloat16* Als = sAl[st];
        const __nv_bfloat16* Bhs = sBh[st];
        const __nv_bfloat16* Bls = sBl[st];

        uint32_t ah[2][4], al[2][4];
        const int c0 = 2 * tig;
#pragma unroll
        for (int mf = 0; mf < 2; mf++) {
            const int r = wm * 32 + mf * 16 + g;
            ah[mf][0] = *(const uint32_t*)(Ahs + r * PADk + c0);
            ah[mf][1] = *(const uint32_t*)(Ahs + (r + 8) * PADk + c0);
            ah[mf][2] = *(const uint32_t*)(Ahs + r * PADk + c0 + 8);
            ah[mf][3] = *(const uint32_t*)(Ahs + (r + 8) * PADk + c0 + 8);
            al[mf][0] = *(const uint32_t*)(Als + r * PADk + c0);
            al[mf][1] = *(const uint32_t*)(Als + (r + 8) * PADk + c0);
            al[mf][2] = *(const uint32_t*)(Als + r * PADk + c0 + 8);
            al[mf][3] = *(const uint32_t*)(Als + (r + 8) * PADk + c0 + 8);
        }
#pragma unroll
        for (int nf = 0; nf < 8; nf++) {
            const int n = wn * 64 + nf * 8 + g;
            const uint32_t bh0 = *(const uint32_t*)(Bhs + n * PADk + c0);
            const uint32_t bh1 = *(const uint32_t*)(Bhs + n * PADk + c0 + 8);
            const uint32_t bl0 = *(const uint32_t*)(Bls + n * PADk + c0);
            const uint32_t bl1 = *(const uint32_t*)(Bls + n * PADk + c0 + 8);
#pragma unroll
            for (int mf = 0; mf < 2; mf++) {
                mma_bf16(acc[mf][nf], ah[mf], bh0, bh1);
                mma_bf16(acc[mf][nf], ah[mf], bl0, bl1);
                mma_bf16(acc[mf][nf], al[mf], bh0, bh1);
            }
        }
    }

    // ---- epilogue ----
#pragma unroll
    for (int mf = 0; mf < 2; mf++) {
#pragma unroll
        for (int nf = 0; nf < 8; nf++) {
            const int r0 = bm + wm * 32 + mf * 16 + g;
            const int cc = bn + wn * 64 + nf * 8 + 2 * tig;
            const float bs0 = bias[cc], bs1 = bias[cc + 1];
            float v0 = acc[mf][nf][0] + bs0;
            float v1 = acc[mf][nf][1] + bs1;
            float v2 = acc[mf][nf][2] + bs0;
            float v3 = acc[mf][nf][3] + bs1;
            const size_t i0 = (size_t)r0 * N + cc;
            const size_t i1 = (size_t)(r0 + 8) * N + cc;
            if (resid) {
                const float2 r0v = *(const float2*)(resid + i0);
                const float2 r1v = *(const float2*)(resid + i1);
                v0 += r0v.x; v1 += r0v.y; v2 += r1v.x; v3 += r1v.y;
            }
            if (relu) {
                v0 = fmaxf(v0, 0.f); v1 = fmaxf(v1, 0.f);
                v2 = fmaxf(v2, 0.f); v3 = fmaxf(v3, 0.f);
            }
            if (C) {
                *(float2*)(C + i0) = make_float2(v0, v1);
                *(float2*)(C + i1) = make_float2(v2, v3);
            }
            if (Ch) {
                __nv_bfloat16 h0, l0, h1, l1, h2, l2, h3, l3;
                bsplit(v0, h0, l0); bsplit(v1, h1, l1);
                bsplit(v2, h2, l2); bsplit(v3, h3, l3);
                *(__nv_bfloat162*)(Ch + i0) = __nv_bfloat162(h0, h1);
                *(__nv_bfloat162*)(Ch + i1) = __nv_bfloat162(h2, h3);
                *(__nv_bfloat162*)(Cl + i0) = __nv_bfloat162(l0, l1);
                *(__nv_bfloat162*)(Cl + i1) = __nv_bfloat162(l2, l3);
            }
        }
    }
}

__global__ __launch_bounds__(256) void gemm16_kernel(
    const __nv_bfloat16* __restrict__ Ah, const __nv_bfloat16* __restrict__ Al,
    const __nv_bfloat16* __restrict__ Bh, const __nv_bfloat16* __restrict__ Bl,
    const float* __restrict__ bias, const float* __restrict__ resid,
    float* __restrict__ C, __nv_bfloat16* __restrict__ Ch, __nv_bfloat16* __restrict__ Cl,
    int M, int N, int K, int relu)
{
    gemm16_core(Ah, Al, Bh, Bl, bias, resid, C, Ch, Cl, M, N, K, relu != 0);
}

// QKV fused via blockIdx.z (B = preconverted transposed weights)
__global__ __launch_bounds__(256) void gemm16_qkv_kernel(
    const __nv_bfloat16* __restrict__ Ah, const __nv_bfloat16* __restrict__ Al,
    const __nv_bfloat16* __restrict__ WTh, const __nv_bfloat16* __restrict__ WTl,
    const float* __restrict__ bq, const float* __restrict__ bk, const float* __restrict__ bv,
    int M, int N, int K)
{
    const size_t off = (size_t)blockIdx.z * Dm * Dm;
    const float* bias; float* C;
    if      (blockIdx.z == 0) { bias = bq; C = g_y; }
    else if (blockIdx.z == 1) { bias = bk; C = g_k; }
    else                      { bias = bv; C = g_v; }
    gemm16_core(Ah, Al, WTh + off, WTl + off, bias, nullptr, C, nullptr, nullptr, M, N, K, false);
}

// ---------------- qe = q @ Erel^T ----------------
__global__ void qe_kernel(const float* __restrict__ er)
{
    int idx = blockIdx.x * blockDim.x + threadIdx.x;
    const int total = Bq * Hh * Sq * NBb;
    if (idx >= total) return;
    int nb = idx % NBb;
    int s  = (idx / NBb) % Sq;
    int h  = (idx / (NBb * Sq)) % Hh;
    int b  =  idx / (NBb * Sq * Hh);
    const float* qr = g_y + ((size_t)(b * Sq + s)) * Dm + h * DHd;
    const float* e  = er + nb * DHd;
    float acc = 0.f;
#pragma unroll
    for (int d = 0; d < DHd; d++) acc = fmaf(qr[d], e[d], acc);
    g_qe[idx] = acc;
}

// ---------------- flash attention (fp32 SIMT), epilogue emits bf16 hi/lo --------
__global__ void attn_kernel(const float* __restrict__ brel, const int* __restrict__ rid)
{
    __shared__ float Qs[64 * 32];
    __shared__ float Ks[64 * 64];
    __shared__ float Vs[64 * 64];
    __shared__ float Cb[32 * NBb];

    int tid = threadIdx.x;
    int tx = tid & 15, ty = tid >> 4;
    int b = blockIdx.z, h = blockIdx.y;
    int q0 = blockIdx.x * 32;

    size_t qbase = ((size_t)(b * Sq) + q0) * Dm + h * DHd;
    for (int i = tid; i < 32 * 16; i += 256) {
        int r = i >> 4, d4 = (i & 15) * 4;
        float4 t = *(const float4*)(g_y + qbase + (size_t)r * Dm + d4);
        Qs[(d4 + 0) * 32 + r] = t.x;
        Qs[(d4 + 1) * 32 + r] = t.y;
        Qs[(d4 + 2) * 32 + r] = t.z;
        Qs[(d4 + 3) * 32 + r] = t.w;
    }
    for (int i = tid; i < 32 * NBb; i += 256) {
        int r = i / NBb, nb = i - r * NBb;
        Cb[i] = g_qe[(((size_t)(b * Hh + h)) * Sq + q0 + r) * NBb + nb] + brel[h * NBb + nb];
    }

    float m_i[2], l_i[2], o[2][4];
#pragma unroll
    for (int i = 0; i < 2; i++) {
        m_i[i] = -CUDART_INF_F; l_i[i] = 0.f;
#pragma unroll
        for (int j = 0; j < 4; j++) o[i][j] = 0.f;
    }
    __syncthreads();

    for (int k0 = 0; k0 < Sq; k0 += 64) {
        size_t kbase = ((size_t)(b * Sq) + k0) * Dm + h * DHd;
        for (int i = tid; i < 64 * 16; i += 256) {
            int r = i >> 4, d4 = (i & 15) * 4;
            float4 tk = *(const float4*)(g_k + kbase + (size_t)r * Dm + d4);
            Ks[(d4 + 0) * 64 + r] = tk.x;
            Ks[(d4 + 1) * 64 + r] = tk.y;
            Ks[(d4 + 2) * 64 + r] = tk.z;
            Ks[(d4 + 3) * 64 + r] = tk.w;
            float4 tv = *(const float4*)(g_v + kbase + (size_t)r * Dm + d4);
            *(float4*)(Vs + r * 64 + d4) = tv;
        }
        __syncthreads();

        float s4[2][4];
#pragma unroll
        for (int i = 0; i < 2; i++)
#pragma unroll
            for (int j = 0; j < 4; j++) s4[i][j] = 0.f;
#pragma unroll
        for (int d = 0; d < 64; d++) {
            float a0 = Qs[d * 32 + ty * 2 + 0];
            float a1 = Qs[d * 32 + ty * 2 + 1];
            float4 bk = *(const float4*)(Ks + d * 64 + tx * 4);
            s4[0][0] = fmaf(a0, bk.x, s4[0][0]);
            s4[0][1] = fmaf(a0, bk.y, s4[0][1]);
            s4[0][2] = fmaf(a0, bk.z, s4[0][2]);
            s4[0][3] = fmaf(a0, bk.w, s4[0][3]);
            s4[1][0] = fmaf(a1, bk.x, s4[1][0]);
            s4[1][1] = fmaf(a1, bk.y, s4[1][1]);
            s4[1][2] = fmaf(a1, bk.z, s4[1][2]);
            s4[1][3] = fmaf(a1, bk.w, s4[1][3]);
        }

#pragma unroll
        for (int i = 0; i < 2; i++) {
            int qr = ty * 2 + i;
            const int* rr = rid + (size_t)(q0 + qr) * Sq + k0 + tx * 4;
            float mt = -CUDART_INF_F;
#pragma unroll
            for (int j = 0; j < 4; j++) {
                float sv = (s4[i][j] + Cb[qr * NBb + rr[j]]) * SCALE_ATTN;
                s4[i][j] = sv;
                mt = fmaxf(mt, sv);
            }
#pragma unroll
            for (int off = 8; off; off >>= 1)
                mt = fmaxf(mt, __shfl_xor_sync(0xffffffffu, mt, off));
            float mnew = fmaxf(m_i[i], mt);
            float fac = __expf(m_i[i] - mnew);
            float rs = 0.f;
#pragma unroll
            for (int j = 0; j < 4; j++) {
                float p = __expf(s4[i][j] - mnew);
                s4[i][j] = p;
                rs += p;
            }
#pragma unroll
            for (int off = 8; off; off >>= 1)
                rs += __shfl_xor_sync(0xffffffffu, rs, off);
            l_i[i] = l_i[i] * fac + rs;
            m_i[i] = mnew;
#pragma unroll
            for (int j = 0; j < 4; j++) o[i][j] *= fac;
        }
        __syncthreads();
#pragma unroll
        for (int i = 0; i < 2; i++)
            *(float4*)(Ks + (ty * 2 + i) * 64 + tx * 4) =
                make_float4(s4[i][0], s4[i][1], s4[i][2], s4[i][3]);
        __syncthreads();

#pragma unroll 8
        for (int kc = 0; kc < 64; kc++) {
            float4 vv = *(const float4*)(Vs + kc * 64 + tx * 4);
#pragma unroll
            for (int i = 0; i < 2; i++) {
                float p = Ks[(ty * 2 + i) * 64 + kc];
                o[i][0] = fmaf(p, vv.x, o[i][0]);
                o[i][1] = fmaf(p, vv.y, o[i][1]);
                o[i][2] = fmaf(p, vv.z, o[i][2]);
                o[i][3] = fmaf(p, vv.w, o[i][3]);
            }
        }
        __syncthreads();
    }

#pragma unroll
    for (int i = 0; i < 2; i++) {
        float inv = 1.f / l_i[i];
        size_t ob = ((size_t)(b * Sq) + q0 + ty * 2 + i) * Dm + h * DHd + tx * 4;
        float f0 = o[i][0] * inv, f1 = o[i][1] * inv, f2 = o[i][2] * inv, f3 = o[i][3] * inv;
        __nv_bfloat16 h0, l0, h1, l1, h2, l2, h3, l3;
        bsplit(f0, h0, l0); bsplit(f1, h1, l1);
        bsplit(f2, h2, l2); bsplit(f3, h3, l3);
        *(__nv_bfloat162*)(g_ah + ob)     = __nv_bfloat162(h0, h1);
        *(__nv_bfloat162*)(g_ah + ob + 2) = __nv_bfloat162(h2, h3);
        *(__nv_bfloat162*)(g_al + ob)     = __nv_bfloat162(l0, l1);
        *(__nv_bfloat162*)(g_al + ob + 2) = __nv_bfloat162(l2, l3);
    }
}

// ---------------- layernorm (+ optional bf16 hi/lo emission) ---------------------
__device__ __forceinline__ float block_sum_256(float val, float* sh) {
#pragma unroll
    for (int off = 16; off; off >>= 1) val += __shfl_xor_sync(0xffffffffu, val, off);
    if ((threadIdx.x & 31) == 0) sh[threadIdx.x >> 5] = val;
    __syncthreads();
    float t = 0.f;
    if (threadIdx.x < 8) t = sh[threadIdx.x];
    if (threadIdx.x < 32) {
#pragma unroll
        for (int off = 4; off; off >>= 1) t += __shfl_xor_sync(0xffffffffu, t, off);
        if (threadIdx.x == 0) sh[0] = t;
    }
    __syncthreads();
    float r = sh[0];
    __syncthreads();
    return r;
}

__global__ void ln_kernel(const float* __restrict__ in, const float* __restrict__ gam,
                          const float* __restrict__ bet, float* __restrict__ out,
                          __nv_bfloat16* __restrict__ oh, __nv_bfloat16* __restrict__ ol)
{
    __shared__ float sh[8];
    int row = blockIdx.x, tid = threadIdx.x;
    float4 x4 = ((const float4*)(in + (size_t)row * Dm))[tid];
    float s = x4.x + x4.y + x4.z + x4.w;
    float mean = block_sum_256(s, sh) * (1.f / Dm);
    float dx = x4.x - mean, dy = x4.y - mean, dz = x4.z - mean, dw = x4.w - mean;
    float s2 = dx * dx + dy * dy + dz * dz + dw * dw;
    float var = block_sum_256(s2, sh) * (1.f / Dm);
    float inv = rsqrtf(var + 1e-6f);
    int c = tid * 4;
    float4 o;
    o.x = dx * inv * gam[c + 0] + bet[c + 0];
    o.y = dy * inv * gam[c + 1] + bet[c + 1];
    o.z = dz * inv * gam[c + 2] + bet[c + 2];
    o.w = dw * inv * gam[c + 3] + bet[c + 3];
    ((float4*)(out + (size_t)row * Dm))[tid] = o;
    if (oh) {
        size_t base = (size_t)row * Dm + c;
        __nv_bfloat16 h0, l0, h1, l1, h2, l2, h3, l3;
        bsplit(o.x, h0, l0); bsplit(o.y, h1, l1);
        bsplit(o.z, h2, l2); bsplit(o.w, h3, l3);
        *(__nv_bfloat162*)(oh + base)     = __nv_bfloat162(h0, h1);
        *(__nv_bfloat162*)(oh + base + 2) = __nv_bfloat162(h2, h3);
        *(__nv_bfloat162*)(ol + base)     = __nv_bfloat162(l0, l1);
        *(__nv_bfloat162*)(ol + base + 2) = __nv_bfloat162(l2, l3);
    }
}

// ---------------- launch ----------------
extern "C" void kernel_launch(void* const* d_in, const int* in_sizes, int n_in,
                              void* d_out, int out_size)
{
    const float* x_in = (const float*)d_in[0];
    const int*   rid  = (const int*)  d_in[1];
    const float* Wq   = (const float*)d_in[2];
    const float* bqp  = (const float*)d_in[3];
    const float* Wk   = (const float*)d_in[4];
    const float* bkp  = (const float*)d_in[5];
    const float* Wv   = (const float*)d_in[6];
    const float* bvp  = (const float*)d_in[7];
    const float* Wo   = (const float*)d_in[8];
    const float* bop  = (const float*)d_in[9];
    const float* Erel = (const float*)d_in[10];
    const float* Brel = (const float*)d_in[11];
    const float* g1   = (const float*)d_in[12];
    const float* be1  = (const float*)d_in[13];
    const float* g2   = (const float*)d_in[14];
    const float* be2  = (const float*)d_in[15];
    const float* W1   = (const float*)d_in[16];
    const float* b1   = (const float*)d_in[17];
    const float* W2   = (const float*)d_in[18];
    const float* b2   = (const float*)d_in[19];
    float* outp = (float*)d_out;

    float *x, *y, *k, *v;
    __nv_bfloat16 *xh, *xl, *ah, *al, *ffh, *ffl, *hh, *hl;
    __nv_bfloat16 *wT4h, *wT4l, *w1Th, *w1Tl, *w2Th, *w2Tl;
    cudaGetSymbolAddress((void**)&x,  g_x);
    cudaGetSymbolAddress((void**)&y,  g_y);
    cudaGetSymbolAddress((void**)&k,  g_k);
    cudaGetSymbolAddress((void**)&v,  g_v);
    cudaGetSymbolAddress((void**)&xh, g_xh);  cudaGetSymbolAddress((void**)&xl, g_xl);
    cudaGetSymbolAddress((void**)&ah, g_ah);  cudaGetSymbolAddress((void**)&al, g_al);
    cudaGetSymbolAddress((void**)&ffh, g_ffh); cudaGetSymbolAddress((void**)&ffl, g_ffl);
    cudaGetSymbolAddress((void**)&hh, g_hh);  cudaGetSymbolAddress((void**)&hl, g_hl);
    cudaGetSymbolAddress((void**)&wT4h, g_wT4h); cudaGetSymbolAddress((void**)&wT4l, g_wT4l);
    cudaGetSymbolAddress((void**)&w1Th, g_w1Th); cudaGetSymbolAddress((void**)&w1Tl, g_w1Tl);
    cudaGetSymbolAddress((void**)&w2Th, g_w2Th); cudaGetSymbolAddress((void**)&w2Tl, g_w2Tl);

    // ---- preconvert all weights (transpose + bf16 split) ----
    const dim3 tb(32, 8);
    for (int l = 0; l < Ll; l++) {
        const size_t wdd = (size_t)l * Dm * Dm;
        const size_t o4  = (size_t)l * 4 * Dm * Dm;
        wconv_kernel<<<dim3(Dm / 32, Dm / 32), tb>>>(Wq + wdd, wT4h + o4,                wT4l + o4,                Dm, Dm);
        wconv_kernel<<<dim3(Dm / 32, Dm / 32), tb>>>(Wk + wdd, wT4h + o4 + (size_t)Dm*Dm,   wT4l + o4 + (size_t)Dm*Dm,   Dm, Dm);
        wconv_kernel<<<dim3(Dm / 32, Dm / 32), tb>>>(Wv + wdd, wT4h + o4 + (size_t)2*Dm*Dm, wT4l + o4 + (size_t)2*Dm*Dm, Dm, Dm);
        wconv_kernel<<<dim3(Dm / 32, Dm / 32), tb>>>(Wo + wdd, wT4h + o4 + (size_t)3*Dm*Dm, wT4l + o4 + (size_t)3*Dm*Dm, Dm, Dm);
        wconv_kernel<<<dim3(Ff / 32, Dm / 32), tb>>>(W1 + (size_t)l * Dm * Ff, w1Th + (size_t)l * Ff * Dm, w1Tl + (size_t)l * Ff * Dm, Dm, Ff);
        wconv_kernel<<<dim3(Dm / 32, Ff / 32), tb>>>(W2 + (size_t)l * Ff * Dm, w2Th + (size_t)l * Dm * Ff, w2Tl + (size_t)l * Dm * Ff, Ff, Dm);
    }

    copy_split_kernel<<<(ROWS * Dm + 255) / 256, 256>>>(x_in, x, xh, xl, ROWS * Dm);

    for (int l = 0; l < Ll; l++) {
        const size_t o4 = (size_t)l * 4 * Dm * Dm;

        // QKV -> fp32 y,k,v
        gemm16_qkv_kernel<<<dim3(Dm / 128, ROWS / 128, 3), 256>>>(
            xh, xl, wT4h + o4, wT4l + o4,
            bqp + l * Dm, bkp + l * Dm, bvp + l * Dm, ROWS, Dm, Dm);

        const int qetot = Bq * Hh * Sq * NBb;
        qe_kernel<<<(qetot + 255) / 256, 256>>>(Erel + (size_t)l * NBb * DHd);

        attn_kernel<<<dim3(Sq / 32, Hh, Bq), 256>>>(Brel + (size_t)l * Hh * NBb, rid);

        // y = attn@Wo + bo + x  (fp32 -> y)
        gemm16_kernel<<<dim3(Dm / 128, ROWS / 128), 256>>>(
            ah, al, wT4h + o4 + (size_t)3 * Dm * Dm, wT4l + o4 + (size_t)3 * Dm * Dm,
            bop + l * Dm, x, y, nullptr, nullptr, ROWS, Dm, Dm, 0);

        // ff_in = LN1(y) -> fp32 k + bf16 ffh/ffl
        ln_kernel<<<ROWS, 256>>>(y, g1 + l * Dm, be1 + l * Dm, k, ffh, ffl);

        // h = relu(ff_in@W1 + b1) -> bf16 hh/hl only
        gemm16_kernel<<<dim3(Ff / 128, ROWS / 128), 256>>>(
            ffh, ffl, w1Th + (size_t)l * Ff * Dm, w1Tl + (size_t)l * Ff * Dm,
            b1 + l * Ff, nullptr, nullptr, hh, hl, ROWS, Ff, Dm, 1);

        // y2 = h@W2 + b2 + ff_in -> fp32 v
        gemm16_kernel<<<dim3(Dm / 128, ROWS / 128), 256>>>(
            hh, hl, w2Th + (size_t)l * Dm * Ff, w2Tl + (size_t)l * Dm * Ff,
            b2 + l * Dm, k, v, nullptr, nullptr, ROWS, Dm, Ff, 0);

        // x = LN2(y2) -> fp32 (+ split for next layer's QKV)
        ln_kernel<<<ROWS, 256>>>(v, g2 + l * Dm, be2 + l * Dm,
                                 (l == Ll - 1) ? outp : x, xh, xl);
    }
}

// round 6
// speedup vs baseline: 2.0917x; 1.1434x over previous
#include <cuda_runtime.h>
#include <cuda_bf16.h>
#include <math_constants.h>
#include <cstdint>

// Problem constants
#define Bq   4
#define Sq   1024
#define Dm   1024
#define Hh   16
#define DHd  64
#define Ff   4096
#define NBb  33
#define Ll   6
#define ROWS (Bq*Sq)
#define SCALE_ATTN 0.125f

// ---------------- scratch (device globals) ----------------
__device__ float g_x [ROWS*Dm];     // layer input fp32 (residual)
__device__ float g_y [ROWS*Dm];     // q / post-Wo fp32
__device__ float g_k [ROWS*Dm];     // k / ff_in fp32
__device__ float g_v [ROWS*Dm];     // v / y2 fp32
__device__ float g_qe[Bq*Hh*Sq*NBb];

__device__ __nv_bfloat16 g_xh [ROWS*Dm], g_xl [ROWS*Dm];
__device__ __nv_bfloat16 g_ah [ROWS*Dm], g_al [ROWS*Dm];
__device__ __nv_bfloat16 g_ffh[ROWS*Dm], g_ffl[ROWS*Dm];
__device__ __nv_bfloat16 g_hh [ROWS*Ff], g_hl [ROWS*Ff];

// transposed bf16 weights: [N][K]
__device__ __nv_bfloat16 g_wT4h[Ll*4*Dm*Dm], g_wT4l[Ll*4*Dm*Dm];
__device__ __nv_bfloat16 g_w1Th[Ll*Ff*Dm],  g_w1Tl[Ll*Ff*Dm];
__device__ __nv_bfloat16 g_w2Th[Ll*Dm*Ff],  g_w2Tl[Ll*Dm*Ff];

__device__ __forceinline__ void bsplit(float f, __nv_bfloat16& h, __nv_bfloat16& l) {
    h = __float2bfloat16_rn(f);
    l = __float2bfloat16_rn(f - __bfloat162float(h));
}

// ---------------- weight transpose + split ----------------
__global__ void wconv_kernel(const float* __restrict__ W,
                             __nv_bfloat16* __restrict__ Th, __nv_bfloat16* __restrict__ Tl,
                             int K, int N)
{
    __shared__ float t[32][33];
    int n0 = blockIdx.x * 32, k0 = blockIdx.y * 32;
    int tx = threadIdx.x, ty = threadIdx.y;
#pragma unroll
    for (int i = 0; i < 4; i++)
        t[ty + 8 * i][tx] = W[(size_t)(k0 + ty + 8 * i) * N + n0 + tx];
    __syncthreads();
#pragma unroll
    for (int i = 0; i < 4; i++) {
        float f = t[tx][ty + 8 * i];
        int n = n0 + ty + 8 * i, k = k0 + tx;
        __nv_bfloat16 h, l; bsplit(f, h, l);
        Th[(size_t)n * K + k] = h;
        Tl[(size_t)n * K + k] = l;
    }
}

// ---------------- copy + split ----------------
__global__ void copy_split_kernel(const float* __restrict__ in, float* __restrict__ out,
                                  __nv_bfloat16* __restrict__ oh, __nv_bfloat16* __restrict__ ol,
                                  int n)
{
    int i = blockIdx.x * blockDim.x + threadIdx.x;
    if (i < n) {
        float f = in[i];
        out[i] = f;
        __nv_bfloat16 h, l; bsplit(f, h, l);
        oh[i] = h; ol[i] = l;
    }
}

// ---------------- bf16 split tensor-core GEMM, cp.async 3-stage ------------------
#define PADk  24                 // 16 data + 8 pad bf16 (48B rows, 16B aligned)
#define CHUNK (128 * PADk)       // bf16 elems per stage per array
#define GEMM_SMEM (4 * 3 * CHUNK * 2)   // 73728 B

__device__ __forceinline__ void mma_bf16(float* c, const uint32_t* a, uint32_t b0, uint32_t b1) {
    asm volatile(
        "mma.sync.aligned.m16n8k16.row.col.f32.bf16.bf16.f32 "
        "{%0,%1,%2,%3}, {%4,%5,%6,%7}, {%8,%9}, {%0,%1,%2,%3};\n"
        : "+f"(c[0]), "+f"(c[1]), "+f"(c[2]), "+f"(c[3])
        : "r"(a[0]), "r"(a[1]), "r"(a[2]), "r"(a[3]), "r"(b0), "r"(b1));
}

__device__ __forceinline__ void cpasync16(__nv_bfloat16* dst, const __nv_bfloat16* src) {
    uint32_t s = (uint32_t)__cvta_generic_to_shared(dst);
    asm volatile("cp.async.cg.shared.global [%0], [%1], 16;\n" :: "r"(s), "l"(src));
}

__device__ __forceinline__ void gemm16_core(
    const __nv_bfloat16* __restrict__ Ah, const __nv_bfloat16* __restrict__ Al,
    const __nv_bfloat16* __restrict__ Bh, const __nv_bfloat16* __restrict__ Bl,
    const float* __restrict__ bias, const float* __restrict__ resid,
    float* __restrict__ C, __nv_bfloat16* __restrict__ Ch, __nv_bfloat16* __restrict__ Cl,
    int M, int N, int K, bool relu)
{
    extern __shared__ __nv_bfloat16 smem[];
    __nv_bfloat16* sAh = smem;
    __nv_bfloat16* sAl = smem + 3 * CHUNK;
    __nv_bfloat16* sBh = smem + 6 * CHUNK;
    __nv_bfloat16* sBl = smem + 9 * CHUNK;

    const int tid  = threadIdx.x;
    const int lane = tid & 31;
    const int warp = tid >> 5;
    const int wm   = warp >> 1;
    const int wn   = warp & 1;
    const int g    = lane >> 2;
    const int tig  = lane & 3;

    const int bm = blockIdx.y * 128, bn = blockIdx.x * 128;
    const int prow = tid >> 1, phalf = (tid & 1) * 8;
    const int so   = prow * PADk + phalf;

    float acc[2][8][4];
#pragma unroll
    for (int i = 0; i < 2; i++)
#pragma unroll
        for (int j = 0; j < 8; j++)
#pragma unroll
            for (int c = 0; c < 4; c++) acc[i][j][c] = 0.f;

    const int nck = K >> 4;

    // prefetch chunks 0,1
#pragma unroll
    for (int pc = 0; pc < 2; pc++) {
        const size_t goA = (size_t)(bm + prow) * K + pc * 16 + phalf;
        const size_t goB = (size_t)(bn + prow) * K + pc * 16 + phalf;
        const int sb = pc * CHUNK + so;
        cpasync16(sAh + sb, Ah + goA);
        cpasync16(sAl + sb, Al + goA);
        cpasync16(sBh + sb, Bh + goB);
        cpasync16(sBl + sb, Bl + goB);
        asm volatile("cp.async.commit_group;\n");
    }

    for (int kc = 0; kc < nck; kc++) {
        if (kc + 2 < nck) asm volatile("cp.async.wait_group 1;\n");
        else              asm volatile("cp.async.wait_group 0;\n");
        __syncthreads();
        if (kc + 2 < nck) {
            const int st = (kc + 2) % 3;
            const size_t goA = (size_t)(bm + prow) * K + (kc + 2) * 16 + phalf;
            const size_t goB = (size_t)(bn + prow) * K + (kc + 2) * 16 + phalf;
            const int sb = st * CHUNK + so;
            cpasync16(sAh + sb, Ah + goA);
            cpasync16(sAl + sb, Al + goA);
            cpasync16(sBh + sb, Bh + goB);
            cpasync16(sBl + sb, Bl + goB);
            asm volatile("cp.async.commit_group;\n");
        }
        const int sb = (kc % 3) * CHUNK;
        const __nv_bfloat16* Ahs = sAh + sb;
        const __nv_bfloat16* Als = sAl + sb;
        const __nv_bfloat16* Bhs = sBh + sb;
        const __nv_bfloat16* Bls = sBl + sb;

        uint32_t ah[2][4], al[2][4];
        const int c0 = 2 * tig;
#pragma unroll
        for (int mf = 0; mf < 2; mf++) {
            const int r = wm * 32 + mf * 16 + g;
            ah[mf][0] = *(const uint32_t*)(Ahs + r * PADk + c0);
            ah[mf][1] = *(const uint32_t*)(Ahs + (r + 8) * PADk + c0);
            ah[mf][2] = *(const uint32_t*)(Ahs + r * PADk + c0 + 8);
            ah[mf][3] = *(const uint32_t*)(Ahs + (r + 8) * PADk + c0 + 8);
            al[mf][0] = *(const uint32_t*)(Als + r * PADk + c0);
            al[mf][1] = *(const uint32_t*)(Als + (r + 8) * PADk + c0);
            al[mf][2] = *(const uint32_t*)(Als + r * PADk + c0 + 8);
            al[mf][3] = *(const uint32_t*)(Als + (r + 8) * PADk + c0 + 8);
        }
#pragma unroll
        for (int nf = 0; nf < 8; nf++) {
            const int n = wn * 64 + nf * 8 + g;
            const uint32_t bh0 = *(const uint32_t*)(Bhs + n * PADk + c0);
            const uint32_t bh1 = *(const uint32_t*)(Bhs + n * PADk + c0 + 8);
            const uint32_t bl0 = *(const uint32_t*)(Bls + n * PADk + c0);
            const uint32_t bl1 = *(const uint32_t*)(Bls + n * PADk + c0 + 8);
#pragma unroll
            for (int mf = 0; mf < 2; mf++) {
                mma_bf16(acc[mf][nf], ah[mf], bh0, bh1);
                mma_bf16(acc[mf][nf], ah[mf], bl0, bl1);
                mma_bf16(acc[mf][nf], al[mf], bh0, bh1);
            }
        }
        __syncthreads();
    }

    // ---- epilogue ----
#pragma unroll
    for (int mf = 0; mf < 2; mf++) {
#pragma unroll
        for (int nf = 0; nf < 8; nf++) {
            const int r0 = bm + wm * 32 + mf * 16 + g;
            const int cc = bn + wn * 64 + nf * 8 + 2 * tig;
            const float bs0 = bias[cc], bs1 = bias[cc + 1];
            float v0 = acc[mf][nf][0] + bs0;
            float v1 = acc[mf][nf][1] + bs1;
            float v2 = acc[mf][nf][2] + bs0;
            float v3 = acc[mf][nf][3] + bs1;
            const size_t i0 = (size_t)r0 * N + cc;
            const size_t i1 = (size_t)(r0 + 8) * N + cc;
            if (resid) {
                const float2 r0v = *(const float2*)(resid + i0);
                const float2 r1v = *(const float2*)(resid + i1);
                v0 += r0v.x; v1 += r0v.y; v2 += r1v.x; v3 += r1v.y;
            }
            if (relu) {
                v0 = fmaxf(v0, 0.f); v1 = fmaxf(v1, 0.f);
                v2 = fmaxf(v2, 0.f); v3 = fmaxf(v3, 0.f);
            }
            if (C) {
                *(float2*)(C + i0) = make_float2(v0, v1);
                *(float2*)(C + i1) = make_float2(v2, v3);
            }
            if (Ch) {
                __nv_bfloat16 h0, l0, h1, l1, h2, l2, h3, l3;
                bsplit(v0, h0, l0); bsplit(v1, h1, l1);
                bsplit(v2, h2, l2); bsplit(v3, h3, l3);
                *(__nv_bfloat162*)(Ch + i0) = __nv_bfloat162(h0, h1);
                *(__nv_bfloat162*)(Ch + i1) = __nv_bfloat162(h2, h3);
                *(__nv_bfloat162*)(Cl + i0) = __nv_bfloat162(l0, l1);
                *(__nv_bfloat162*)(Cl + i1) = __nv_bfloat162(l2, l3);
            }
        }
    }
}

__global__ __launch_bounds__(256) void gemm16_kernel(
    const __nv_bfloat16* __restrict__ Ah, const __nv_bfloat16* __restrict__ Al,
    const __nv_bfloat16* __restrict__ Bh, const __nv_bfloat16* __restrict__ Bl,
    const float* __restrict__ bias, const float* __restrict__ resid,
    float* __restrict__ C, __nv_bfloat16* __restrict__ Ch, __nv_bfloat16* __restrict__ Cl,
    int M, int N, int K, int relu)
{
    gemm16_core(Ah, Al, Bh, Bl, bias, resid, C, Ch, Cl, M, N, K, relu != 0);
}

__global__ __launch_bounds__(256) void gemm16_qkv_kernel(
    const __nv_bfloat16* __restrict__ Ah, const __nv_bfloat16* __restrict__ Al,
    const __nv_bfloat16* __restrict__ WTh, const __nv_bfloat16* __restrict__ WTl,
    const float* __restrict__ bq, const float* __restrict__ bk, const float* __restrict__ bv,
    int M, int N, int K)
{
    const size_t off = (size_t)blockIdx.z * Dm * Dm;
    const float* bias; float* C;
    if      (blockIdx.z == 0) { bias = bq; C = g_y; }
    else if (blockIdx.z == 1) { bias = bk; C = g_k; }
    else                      { bias = bv; C = g_v; }
    gemm16_core(Ah, Al, WTh + off, WTl + off, bias, nullptr, C, nullptr, nullptr, M, N, K, false);
}

// ---------------- qe = q @ Erel^T ----------------
__global__ void qe_kernel(const float* __restrict__ er)
{
    int idx = blockIdx.x * blockDim.x + threadIdx.x;
    const int total = Bq * Hh * Sq * NBb;
    if (idx >= total) return;
    int nb = idx % NBb;
    int s  = (idx / NBb) % Sq;
    int h  = (idx / (NBb * Sq)) % Hh;
    int b  =  idx / (NBb * Sq * Hh);
    const float* qr = g_y + ((size_t)(b * Sq + s)) * Dm + h * DHd;
    const float* e  = er + nb * DHd;
    float acc = 0.f;
#pragma unroll
    for (int d = 0; d < DHd; d++) acc = fmaf(qr[d], e[d], acc);
    g_qe[idx] = acc;
}

// ---------------- flash attention: 64q x 64k tile, 4x4/thread -------------------
// dynamic smem: Qs 16K + Ks/P 16K + Vs 16K + Cb 8.45K = 57600 B
#define ATTN_SMEM ((64 * 64 * 3 + 64 * NBb) * 4)

__global__ void attn_kernel(const float* __restrict__ brel, const int* __restrict__ rid)
{
    extern __shared__ float sm[];
    float* Qs = sm;                // [d][qr] d-major
    float* Ks = sm + 4096;         // [d][kc] d-major; reused as P[qr][kc]
    float* Vs = sm + 8192;         // [kc][dh]
    float* Cb = sm + 12288;        // [64][NBb]

    int tid = threadIdx.x;
    int tx = tid & 15, ty = tid >> 4;
    int b = blockIdx.z, h = blockIdx.y;
    int q0 = blockIdx.x * 64;

    size_t qbase = ((size_t)(b * Sq) + q0) * Dm + h * DHd;
    for (int i = tid; i < 64 * 16; i += 256) {
        int r = i >> 4, d4 = (i & 15) * 4;
        float4 t = *(const float4*)(g_y + qbase + (size_t)r * Dm + d4);
        Qs[(d4 + 0) * 64 + r] = t.x;
        Qs[(d4 + 1) * 64 + r] = t.y;
        Qs[(d4 + 2) * 64 + r] = t.z;
        Qs[(d4 + 3) * 64 + r] = t.w;
    }
    for (int i = tid; i < 64 * NBb; i += 256) {
        int r = i / NBb, nb = i - r * NBb;
        Cb[i] = g_qe[(((size_t)(b * Hh + h)) * Sq + q0 + r) * NBb + nb] + brel[h * NBb + nb];
    }

    float m_i[4], l_i[4], o[4][4];
#pragma unroll
    for (int i = 0; i < 4; i++) {
        m_i[i] = -CUDART_INF_F; l_i[i] = 0.f;
#pragma unroll
        for (int j = 0; j < 4; j++) o[i][j] = 0.f;
    }
    __syncthreads();

    for (int k0 = 0; k0 < Sq; k0 += 64) {
        size_t kbase = ((size_t)(b * Sq) + k0) * Dm + h * DHd;
        for (int i = tid; i < 64 * 16; i += 256) {
            int r = i >> 4, d4 = (i & 15) * 4;
            float4 tk = *(const float4*)(g_k + kbase + (size_t)r * Dm + d4);
            Ks[(d4 + 0) * 64 + r] = tk.x;
            Ks[(d4 + 1) * 64 + r] = tk.y;
            Ks[(d4 + 2) * 64 + r] = tk.z;
            Ks[(d4 + 3) * 64 + r] = tk.w;
            float4 tv = *(const float4*)(g_v + kbase + (size_t)r * Dm + d4);
            *(float4*)(Vs + r * 64 + d4) = tv;
        }
        __syncthreads();

        // S = Q K^T, 4x4 per thread
        float s4[4][4];
#pragma unroll
        for (int i = 0; i < 4; i++)
#pragma unroll
            for (int j = 0; j < 4; j++) s4[i][j] = 0.f;
#pragma unroll
        for (int d = 0; d < 64; d++) {
            float4 aq = *(const float4*)(Qs + d * 64 + ty * 4);
            float4 bk = *(const float4*)(Ks + d * 64 + tx * 4);
            float a_[4] = {aq.x, aq.y, aq.z, aq.w};
            float b_[4] = {bk.x, bk.y, bk.z, bk.w};
#pragma unroll
            for (int i = 0; i < 4; i++)
#pragma unroll
                for (int j = 0; j < 4; j++)
                    s4[i][j] = fmaf(a_[i], b_[j], s4[i][j]);
        }

        // rel terms + online softmax (row = 16 lanes same ty)
#pragma unroll
        for (int i = 0; i < 4; i++) {
            int qr = ty * 4 + i;
            const int* rr = rid + (size_t)(q0 + qr) * Sq + k0 + tx * 4;
            float mt = -CUDART_INF_F;
#pragma unroll
            for (int j = 0; j < 4; j++) {
                float sv = (s4[i][j] + Cb[qr * NBb + rr[j]]) * SCALE_ATTN;
                s4[i][j] = sv;
                mt = fmaxf(mt, sv);
            }
#pragma unroll
            for (int off = 8; off; off >>= 1)
                mt = fmaxf(mt, __shfl_xor_sync(0xffffffffu, mt, off));
            float mnew = fmaxf(m_i[i], mt);
            float fac = __expf(m_i[i] - mnew);
            float rs = 0.f;
#pragma unroll
            for (int j = 0; j < 4; j++) {
                float p = __expf(s4[i][j] - mnew);
                s4[i][j] = p;
                rs += p;
            }
#pragma unroll
            for (int off = 8; off; off >>= 1)
                rs += __shfl_xor_sync(0xffffffffu, rs, off);
            l_i[i] = l_i[i] * fac + rs;
            m_i[i] = mnew;
#pragma unroll
            for (int j = 0; j < 4; j++) o[i][j] *= fac;
        }
        __syncthreads();
#pragma unroll
        for (int i = 0; i < 4; i++)
            *(float4*)(Ks + (ty * 4 + i) * 64 + tx * 4) =
                make_float4(s4[i][0], s4[i][1], s4[i][2], s4[i][3]);
        __syncthreads();

        // O += P V
#pragma unroll 8
        for (int kc = 0; kc < 64; kc++) {
            float4 vv = *(const float4*)(Vs + kc * 64 + tx * 4);
#pragma unroll
            for (int i = 0; i < 4; i++) {
                float p = Ks[(ty * 4 + i) * 64 + kc];
                o[i][0] = fmaf(p, vv.x, o[i][0]);
                o[i][1] = fmaf(p, vv.y, o[i][1]);
                o[i][2] = fmaf(p, vv.z, o[i][2]);
                o[i][3] = fmaf(p, vv.w, o[i][3]);
            }
        }
        __syncthreads();
    }

    // epilogue -> bf16 hi/lo
#pragma unroll
    for (int i = 0; i < 4; i++) {
        float inv = 1.f / l_i[i];
        size_t ob = ((size_t)(b * Sq) + q0 + ty * 4 + i) * Dm + h * DHd + tx * 4;
        float f0 = o[i][0] * inv, f1 = o[i][1] * inv, f2 = o[i][2] * inv, f3 = o[i][3] * inv;
        __nv_bfloat16 h0, l0, h1, l1, h2, l2, h3, l3;
        bsplit(f0, h0, l0); bsplit(f1, h1, l1);
        bsplit(f2, h2, l2); bsplit(f3, h3, l3);
        *(__nv_bfloat162*)(g_ah + ob)     = __nv_bfloat162(h0, h1);
        *(__nv_bfloat162*)(g_ah + ob + 2) = __nv_bfloat162(h2, h3);
        *(__nv_bfloat162*)(g_al + ob)     = __nv_bfloat162(l0, l1);
        *(__nv_bfloat162*)(g_al + ob + 2) = __nv_bfloat162(l2, l3);
    }
}

// ---------------- layernorm ----------------
__device__ __forceinline__ float block_sum_256(float val, float* sh) {
#pragma unroll
    for (int off = 16; off; off >>= 1) val += __shfl_xor_sync(0xffffffffu, val, off);
    if ((threadIdx.x & 31) == 0) sh[threadIdx.x >> 5] = val;
    __syncthreads();
    float t = 0.f;
    if (threadIdx.x < 8) t = sh[threadIdx.x];
    if (threadIdx.x < 32) {
#pragma unroll
        for (int off = 4; off; off >>= 1) t += __shfl_xor_sync(0xffffffffu, t, off);
        if (threadIdx.x == 0) sh[0] = t;
    }
    __syncthreads();
    float r = sh[0];
    __syncthreads();
    return r;
}

__global__ void ln_kernel(const float* __restrict__ in, const float* __restrict__ gam,
                          const float* __restrict__ bet, float* __restrict__ out,
                          __nv_bfloat16* __restrict__ oh, __nv_bfloat16* __restrict__ ol)
{
    __shared__ float sh[8];
    int row = blockIdx.x, tid = threadIdx.x;
    float4 x4 = ((const float4*)(in + (size_t)row * Dm))[tid];
    float s = x4.x + x4.y + x4.z + x4.w;
    float mean = block_sum_256(s, sh) * (1.f / Dm);
    float dx = x4.x - mean, dy = x4.y - mean, dz = x4.z - mean, dw = x4.w - mean;
    float s2 = dx * dx + dy * dy + dz * dz + dw * dw;
    float var = block_sum_256(s2, sh) * (1.f / Dm);
    float inv = rsqrtf(var + 1e-6f);
    int c = tid * 4;
    float4 o;
    o.x = dx * inv * gam[c + 0] + bet[c + 0];
    o.y = dy * inv * gam[c + 1] + bet[c + 1];
    o.z = dz * inv * gam[c + 2] + bet[c + 2];
    o.w = dw * inv * gam[c + 3] + bet[c + 3];
    ((float4*)(out + (size_t)row * Dm))[tid] = o;
    if (oh) {
        size_t base = (size_t)row * Dm + c;
        __nv_bfloat16 h0, l0, h1, l1, h2, l2, h3, l3;
        bsplit(o.x, h0, l0); bsplit(o.y, h1, l1);
        bsplit(o.z, h2, l2); bsplit(o.w, h3, l3);
        *(__nv_bfloat162*)(oh + base)     = __nv_bfloat162(h0, h1);
        *(__nv_bfloat162*)(oh + base + 2) = __nv_bfloat162(h2, h3);
        *(__nv_bfloat162*)(ol + base)     = __nv_bfloat162(l0, l1);
        *(__nv_bfloat162*)(ol + base + 2) = __nv_bfloat162(l2, l3);
    }
}

// ---------------- launch ----------------
extern "C" void kernel_launch(void* const* d_in, const int* in_sizes, int n_in,
                              void* d_out, int out_size)
{
    const float* x_in = (const float*)d_in[0];
    const int*   rid  = (const int*)  d_in[1];
    const float* Wq   = (const float*)d_in[2];
    const float* bqp  = (const float*)d_in[3];
    const float* Wk   = (const float*)d_in[4];
    const float* bkp  = (const float*)d_in[5];
    const float* Wv   = (const float*)d_in[6];
    const float* bvp  = (const float*)d_in[7];
    const float* Wo   = (const float*)d_in[8];
    const float* bop  = (const float*)d_in[9];
    const float* Erel = (const float*)d_in[10];
    const float* Brel = (const float*)d_in[11];
    const float* g1   = (const float*)d_in[12];
    const float* be1  = (const float*)d_in[13];
    const float* g2   = (const float*)d_in[14];
    const float* be2  = (const float*)d_in[15];
    const float* W1   = (const float*)d_in[16];
    const float* b1   = (const float*)d_in[17];
    const float* W2   = (const float*)d_in[18];
    const float* b2   = (const float*)d_in[19];
    float* outp = (float*)d_out;

    float *x, *y, *k, *v;
    __nv_bfloat16 *xh, *xl, *ah, *al, *ffh, *ffl, *hh, *hl;
    __nv_bfloat16 *wT4h, *wT4l, *w1Th, *w1Tl, *w2Th, *w2Tl;
    cudaGetSymbolAddress((void**)&x,  g_x);
    cudaGetSymbolAddress((void**)&y,  g_y);
    cudaGetSymbolAddress((void**)&k,  g_k);
    cudaGetSymbolAddress((void**)&v,  g_v);
    cudaGetSymbolAddress((void**)&xh, g_xh);  cudaGetSymbolAddress((void**)&xl, g_xl);
    cudaGetSymbolAddress((void**)&ah, g_ah);  cudaGetSymbolAddress((void**)&al, g_al);
    cudaGetSymbolAddress((void**)&ffh, g_ffh); cudaGetSymbolAddress((void**)&ffl, g_ffl);
    cudaGetSymbolAddress((void**)&hh, g_hh);  cudaGetSymbolAddress((void**)&hl, g_hl);
    cudaGetSymbolAddress((void**)&wT4h, g_wT4h); cudaGetSymbolAddress((void**)&wT4l, g_wT4l);
    cudaGetSymbolAddress((void**)&w1Th, g_w1Th); cudaGetSymbolAddress((void**)&w1Tl, g_w1Tl);
    cudaGetSymbolAddress((void**)&w2Th, g_w2Th); cudaGetSymbolAddress((void**)&w2Tl, g_w2Tl);

    cudaFuncSetAttribute(gemm16_kernel,     cudaFuncAttributeMaxDynamicSharedMemorySize, GEMM_SMEM);
    cudaFuncSetAttribute(gemm16_qkv_kernel, cudaFuncAttributeMaxDynamicSharedMemorySize, GEMM_SMEM);
    cudaFuncSetAttribute(attn_kernel,       cudaFuncAttributeMaxDynamicSharedMemorySize, ATTN_SMEM);

    // ---- preconvert all weights ----
    const dim3 tb(32, 8);
    for (int l = 0; l < Ll; l++) {
        const size_t wdd = (size_t)l * Dm * Dm;
        const size_t o4  = (size_t)l * 4 * Dm * Dm;
        wconv_kernel<<<dim3(Dm / 32, Dm / 32), tb>>>(Wq + wdd, wT4h + o4,                   wT4l + o4,                   Dm, Dm);
        wconv_kernel<<<dim3(Dm / 32, Dm / 32), tb>>>(Wk + wdd, wT4h + o4 + (size_t)Dm*Dm,   wT4l + o4 + (size_t)Dm*Dm,   Dm, Dm);
        wconv_kernel<<<dim3(Dm / 32, Dm / 32), tb>>>(Wv + wdd, wT4h + o4 + (size_t)2*Dm*Dm, wT4l + o4 + (size_t)2*Dm*Dm, Dm, Dm);
        wconv_kernel<<<dim3(Dm / 32, Dm / 32), tb>>>(Wo + wdd, wT4h + o4 + (size_t)3*Dm*Dm, wT4l + o4 + (size_t)3*Dm*Dm, Dm, Dm);
        wconv_kernel<<<dim3(Ff / 32, Dm / 32), tb>>>(W1 + (size_t)l * Dm * Ff, w1Th + (size_t)l * Ff * Dm, w1Tl + (size_t)l * Ff * Dm, Dm, Ff);
        wconv_kernel<<<dim3(Dm / 32, Ff / 32), tb>>>(W2 + (size_t)l * Ff * Dm, w2Th + (size_t)l * Dm * Ff, w2Tl + (size_t)l * Dm * Ff, Ff, Dm);
    }

    copy_split_kernel<<<(ROWS * Dm + 255) / 256, 256>>>(x_in, x, xh, xl, ROWS * Dm);

    for (int l = 0; l < Ll; l++) {
        const size_t o4 = (size_t)l * 4 * Dm * Dm;

        gemm16_qkv_kernel<<<dim3(Dm / 128, ROWS / 128, 3), 256, GEMM_SMEM>>>(
            xh, xl, wT4h + o4, wT4l + o4,
            bqp + l * Dm, bkp + l * Dm, bvp + l * Dm, ROWS, Dm, Dm);

        const int qetot = Bq * Hh * Sq * NBb;
        qe_kernel<<<(qetot + 255) / 256, 256>>>(Erel + (size_t)l * NBb * DHd);

        attn_kernel<<<dim3(Sq / 64, Hh, Bq), 256, ATTN_SMEM>>>(Brel + (size_t)l * Hh * NBb, rid);

        gemm16_kernel<<<dim3(Dm / 128, ROWS / 128), 256, GEMM_SMEM>>>(
            ah, al, wT4h + o4 + (size_t)3 * Dm * Dm, wT4l + o4 + (size_t)3 * Dm * Dm,
            bop + l * Dm, x, y, nullptr, nullptr, ROWS, Dm, Dm, 0);

        ln_kernel<<<ROWS, 256>>>(y, g1 + l * Dm, be1 + l * Dm, k, ffh, ffl);

        gemm16_kernel<<<dim3(Ff / 128, ROWS / 128), 256, GEMM_SMEM>>>(
            ffh, ffl, w1Th + (size_t)l * Ff * Dm, w1Tl + (size_t)l * Ff * Dm,
            b1 + l * Ff, nullptr, nullptr, hh, hl, ROWS, Ff, Dm, 1);

        gemm16_kernel<<<dim3(Dm / 128, ROWS / 128), 256, GEMM_SMEM>>>(
            hh, hl, w2Th + (size_t)l * Dm * Ff, w2Tl + (size_t)l * Dm * Ff,
            b2 + l * Dm, k, v, nullptr, nullptr, ROWS, Dm, Ff, 0);

        ln_kernel<<<ROWS, 256>>>(v, g2 + l * Dm, be2 + l * Dm,
                                 (l == Ll - 1) ? outp : x, xh, xl);
    }
}